// round 3
// baseline (speedup 1.0000x reference)
#include <cuda_runtime.h>
#include <cstdint>

#define THREADS 256

// ---------------------------------------------------------------------------
// Fused LSTM cell via mma.sync.m16n8k8.tf32 (legacy HMMA path; tcgen05 is
// 'a'-gated and unavailable at PTX target sm_103).
//   preact = [x|h|s|t] @ [Wx;Wh;Ws;Wt] + b   (16384 x 2048, K = 1024)
// CTA tile: 128 rows x 256 preact cols (= 64 hidden cols x 4 gates).
// 8 warps in 2(M) x 4(N), warp tile 64x64 -> LDS-per-mma = 1.0 (was 2.25).
// Preact col mapping n = wn*64 + (fh*4 + gate)*8 + r keeps all 4 gates of a
// hidden col in ONE thread -> register-local epilogue.
// 3-stage smem pipeline, LDG one chunk ahead of STS.
// ---------------------------------------------------------------------------

static constexpr int ASTRIDE     = 20;                  // words, conflict-free
static constexpr int BSTRIDE     = 264;                 // words, bank = 8*tig+gid
static constexpr int A_WORDS     = 128 * ASTRIDE;       // 2560
static constexpr int B_WORDS     = 16 * BSTRIDE;        // 4224
static constexpr int STAGE_WORDS = A_WORDS + B_WORDS;   // 6784
static constexpr int NSTAGE      = 3;
static constexpr int BIAS_OFF    = NSTAGE * STAGE_WORDS;
static constexpr int SMEM_WORDS  = BIAS_OFF + 256;
static constexpr int SMEM_BYTES  = SMEM_WORDS * 4;      // 82432

__device__ __forceinline__ uint32_t f2tf32(float f) {
    uint32_t u;
    asm("cvt.rna.tf32.f32 %0, %1;" : "=r"(u) : "f"(f));
    return u;
}

__device__ __forceinline__ void mma_tf32(float* d, const uint32_t* a,
                                         uint32_t b0, uint32_t b1) {
    asm volatile(
        "mma.sync.aligned.m16n8k8.row.col.f32.tf32.tf32.f32 "
        "{%0,%1,%2,%3}, {%4,%5,%6,%7}, {%8,%9}, {%0,%1,%2,%3};\n"
        : "+f"(d[0]), "+f"(d[1]), "+f"(d[2]), "+f"(d[3])
        : "r"(a[0]), "r"(a[1]), "r"(a[2]), "r"(a[3]), "r"(b0), "r"(b1));
}

__device__ __forceinline__ float fast_sigmoid(float v) {
    return 1.0f / (1.0f + __expf(-v));
}
__device__ __forceinline__ float fast_tanh(float v) {
    float x = fminf(fmaxf(v, -20.0f), 20.0f);
    float e = __expf(2.0f * x);
    return (e - 1.0f) / (e + 1.0f);
}

__global__ __launch_bounds__(THREADS, 1)
void lstm_mma_v2(const float* __restrict__ x,  const float* __restrict__ hin,
                 const float* __restrict__ cin, const float* __restrict__ sp,
                 const float* __restrict__ tp,
                 const float* __restrict__ Wx, const float* __restrict__ Wh,
                 const float* __restrict__ bh, const float* __restrict__ Ws,
                 const float* __restrict__ Wt,
                 float* __restrict__ out, int B)
{
    extern __shared__ __align__(16) uint32_t sm[];

    const int tid  = threadIdx.x;
    const int wid  = tid >> 5;
    const int lane = tid & 31;
    const int gid  = lane >> 2;      // 0..7
    const int tig  = lane & 3;       // 0..3
    const int wm   = wid & 1;        // M half
    const int wn   = wid >> 1;       // 0..3, N quarter
    const int m0   = blockIdx.x * 128;
    const int j0   = blockIdx.y * 64;

    float acc[4][8][4];              // [mb][f][c]  f = fh*4 + gate
#pragma unroll
    for (int mb = 0; mb < 4; mb++)
#pragma unroll
        for (int f = 0; f < 8; f++)
#pragma unroll
            for (int q = 0; q < 4; q++) acc[mb][f][q] = 0.0f;

    float4 fa[2], fb[4];

    // ---- LDG one K16 chunk into registers -------------------------------
    auto ldg_chunk = [&](int s) {
        const int kg = s * 16;
        const float* ap; int astr, kl;
        if (kg < 256)      { ap = x;   astr = 256; kl = kg;       }
        else if (kg < 768) { ap = hin; astr = 512; kl = kg - 256; }
        else if (kg < 896) { ap = sp;  astr = 128; kl = kg - 768; }
        else               { ap = tp;  astr = 128; kl = kg - 896; }
        const float* wp;
        if (kg < 256)      wp = Wx + (size_t)kl * 2048;
        else if (kg < 768) wp = Wh + (size_t)kl * 2048;
        else if (kg < 896) wp = Ws + (size_t)kl * 2048;
        else               wp = Wt + (size_t)kl * 2048;

        // A: 128 rows x 16 k = 512 float4, 2 per thread
#pragma unroll
        for (int i = 0; i < 2; i++) {
            const int v = tid + i * 256;
            const int row = v >> 2, kq = v & 3;
            fa[i] = *reinterpret_cast<const float4*>(
                ap + (size_t)(m0 + row) * astr + kl + kq * 4);
        }
        // B: 16 k x 256 n = 1024 float4, 4 per thread; 256B-contiguous runs
#pragma unroll
        for (int i = 0; i < 4; i++) {
            const int v = tid + i * 256;
            const int k = v >> 6, w6 = v & 63;
            const int gate = w6 >> 4, jq = w6 & 15;
            fb[i] = *reinterpret_cast<const float4*>(
                wp + (size_t)k * 2048 + gate * 512 + j0 + jq * 4);
        }
    };

    // ---- STS the registered chunk into stage st --------------------------
    auto sts_chunk = [&](int st) {
        uint32_t* As = sm + st * STAGE_WORDS;
        uint32_t* Bs = As + A_WORDS;
#pragma unroll
        for (int i = 0; i < 2; i++) {
            const int v = tid + i * 256;
            const int row = v >> 2, kq = v & 3;
            *reinterpret_cast<uint4*>(As + row * ASTRIDE + kq * 4) =
                make_uint4(f2tf32(fa[i].x), f2tf32(fa[i].y),
                           f2tf32(fa[i].z), f2tf32(fa[i].w));
        }
#pragma unroll
        for (int i = 0; i < 4; i++) {
            const int v = tid + i * 256;
            const int k = v >> 6, w6 = v & 63;
            const int gate = w6 >> 4, jq = w6 & 15;
            // n = (jq>>2)*64 + ((jq>>1)&1)*32 + gate*8 + (jq&1)*4
            const int n = (jq >> 2) * 64 + ((jq >> 1) & 1) * 32 + gate * 8 +
                          (jq & 1) * 4;
            *reinterpret_cast<uint4*>(Bs + k * BSTRIDE + n) =
                make_uint4(f2tf32(fb[i].x), f2tf32(fb[i].y),
                           f2tf32(fb[i].z), f2tf32(fb[i].w));
        }
    };

    // ---- compute one K16 chunk from stage st -----------------------------
    auto compute = [&](int st) {
        const uint32_t* As = sm + st * STAGE_WORDS;
        const uint32_t* Bs = As + A_WORDS;
#pragma unroll
        for (int ks = 0; ks < 2; ks++) {
            const int ko = ks * 8;
            uint32_t a[4][4];
#pragma unroll
            for (int mb = 0; mb < 4; mb++) {
                const int rb = wm * 64 + mb * 16;
                a[mb][0] = As[(rb + gid)     * ASTRIDE + ko + tig];
                a[mb][1] = As[(rb + gid + 8) * ASTRIDE + ko + tig];
                a[mb][2] = As[(rb + gid)     * ASTRIDE + ko + tig + 4];
                a[mb][3] = As[(rb + gid + 8) * ASTRIDE + ko + tig + 4];
            }
            uint32_t b[8][2];
#pragma unroll
            for (int f = 0; f < 8; f++) {
                const int nn = wn * 64 + f * 8 + gid;
                b[f][0] = Bs[(ko + tig)     * BSTRIDE + nn];
                b[f][1] = Bs[(ko + tig + 4) * BSTRIDE + nn];
            }
#pragma unroll
            for (int f = 0; f < 8; f++)
#pragma unroll
                for (int mb = 0; mb < 4; mb++)
                    mma_tf32(acc[mb][f], a[mb], b[f][0], b[f][1]);
        }
    };

    // ---- prologue --------------------------------------------------------
    ldg_chunk(0);
    sts_chunk(0);
    ldg_chunk(1);
    {   // bias: bhs[gate*64 + jl]
        const int gate = tid >> 6, jl = tid & 63;
        ((float*)(sm + BIAS_OFF))[tid] = bh[gate * 512 + j0 + jl];
    }
    __syncthreads();

    // ---- main loop: 64 chunks -------------------------------------------
#pragma unroll 1
    for (int s = 0; s < 64; s++) {
        if (s + 1 < 64) sts_chunk((s + 1) % 3);   // regs hold chunk s+1
        if (s + 2 < 64) ldg_chunk(s + 2);
        compute(s % 3);
        __syncthreads();
    }

    // ---- epilogue: register-local gates ----------------------------------
    const float* bhs = (const float*)(sm + BIAS_OFF);
#pragma unroll
    for (int mb = 0; mb < 4; mb++) {
#pragma unroll
        for (int fh = 0; fh < 2; fh++) {
#pragma unroll
            for (int q = 0; q < 2; q++) {
                const int jl = wn * 16 + fh * 8 + 2 * tig + q;
                const int j  = j0 + jl;
                const float bi = bhs[0 * 64 + jl];
                const float bf = bhs[1 * 64 + jl];
                const float bo = bhs[2 * 64 + jl];
                const float bc = bhs[3 * 64 + jl];
#pragma unroll
                for (int rh = 0; rh < 2; rh++) {
                    const int row  = m0 + wm * 64 + mb * 16 + gid + 8 * rh;
                    const int cidx = rh * 2 + q;
                    const float pi = acc[mb][fh * 4 + 0][cidx] + bi;
                    const float pf = acc[mb][fh * 4 + 1][cidx] + bf;
                    const float po = acc[mb][fh * 4 + 2][cidx] + bo;
                    const float pc = acc[mb][fh * 4 + 3][cidx] + bc;
                    const float ig = fast_sigmoid(pi);
                    const float fg = fast_sigmoid(pf);
                    const float og = fast_sigmoid(po);
                    const float cg = fast_tanh(pc);
                    const float cn = fg * cin[(size_t)row * 512 + j] + ig * cg;
                    out[(size_t)row * 512 + j] = fast_tanh(og * cn);
                    out[(size_t)B * 512 + (size_t)row * 512 + j] = cn;
                }
            }
        }
    }
}

extern "C" void kernel_launch(void* const* d_in, const int* in_sizes, int n_in,
                              void* d_out, int out_size) {
    const float* x  = (const float*)d_in[0];
    const float* h  = (const float*)d_in[1];
    const float* c  = (const float*)d_in[2];
    const float* sp = (const float*)d_in[3];
    const float* tp = (const float*)d_in[4];
    const float* Wx = (const float*)d_in[5];
    const float* Wh = (const float*)d_in[6];
    const float* bh = (const float*)d_in[7];
    const float* Ws = (const float*)d_in[8];
    const float* Wt = (const float*)d_in[9];
    float* out = (float*)d_out;

    const int B = in_sizes[0] / 256;   // x is [B, 256]
    cudaFuncSetAttribute(lstm_mma_v2,
                         cudaFuncAttributeMaxDynamicSharedMemorySize, SMEM_BYTES);
    dim3 grid(B / 128, 8);
    lstm_mma_v2<<<grid, THREADS, SMEM_BYTES>>>(x, h, c, sp, tp,
                                               Wx, Wh, bh, Ws, Wt, out, B);
}

// round 4
// speedup vs baseline: 1.0546x; 1.0546x over previous
#include <cuda_runtime.h>
#include <cstdint>

#define THREADS 512

// ---------------------------------------------------------------------------
// Fused LSTM cell via mma.sync.m16n8k8.tf32 (tcgen05 unavailable: ptxas
// target is sm_103 without 'a' suffix).
//   preact = [x|h|s|t] @ [Wx;Wh;Ws;Wt] + b   (16384 x 2048, K = 1024)
// CTA tile: 128 rows x 256 preact cols, 512 threads = 16 warps in 4(M)x4(N),
// warp tile 32x64 -> 64 accum regs/thread -> ~128 regs -> 16 warps/SM.
// 3-stage smem pipeline (strides 20 / 264, conflict-free), LDG 2 chunks ahead.
// Col mapping n = wn*64 + (fh*4+gate)*8 + r keeps all 4 gates of a hidden
// column in one thread -> register-local epilogue.
// ---------------------------------------------------------------------------

static constexpr int ASTRIDE     = 20;                  // words
static constexpr int BSTRIDE     = 264;                 // words
static constexpr int A_WORDS     = 128 * ASTRIDE;       // 2560
static constexpr int B_WORDS     = 16 * BSTRIDE;        // 4224
static constexpr int STAGE_WORDS = A_WORDS + B_WORDS;   // 6784
static constexpr int NSTAGE      = 3;
static constexpr int BIAS_OFF    = NSTAGE * STAGE_WORDS;
static constexpr int SMEM_WORDS  = BIAS_OFF + 256;
static constexpr int SMEM_BYTES  = SMEM_WORDS * 4;      // 82432

__device__ __forceinline__ uint32_t f2tf32(float f) {
    uint32_t u;
    asm("cvt.rna.tf32.f32 %0, %1;" : "=r"(u) : "f"(f));
    return u;
}

__device__ __forceinline__ void mma_tf32(float* d, const uint32_t* a,
                                         uint32_t b0, uint32_t b1) {
    asm volatile(
        "mma.sync.aligned.m16n8k8.row.col.f32.tf32.tf32.f32 "
        "{%0,%1,%2,%3}, {%4,%5,%6,%7}, {%8,%9}, {%0,%1,%2,%3};\n"
        : "+f"(d[0]), "+f"(d[1]), "+f"(d[2]), "+f"(d[3])
        : "r"(a[0]), "r"(a[1]), "r"(a[2]), "r"(a[3]), "r"(b0), "r"(b1));
}

__device__ __forceinline__ float fast_sigmoid(float v) {
    return 1.0f / (1.0f + __expf(-v));
}
__device__ __forceinline__ float fast_tanh(float v) {
    float x = fminf(fmaxf(v, -20.0f), 20.0f);
    float e = __expf(2.0f * x);
    return (e - 1.0f) / (e + 1.0f);
}

__global__ __launch_bounds__(THREADS, 1)
void lstm_mma_v3(const float* __restrict__ x,  const float* __restrict__ hin,
                 const float* __restrict__ cin, const float* __restrict__ sp,
                 const float* __restrict__ tp,
                 const float* __restrict__ Wx, const float* __restrict__ Wh,
                 const float* __restrict__ bh, const float* __restrict__ Ws,
                 const float* __restrict__ Wt,
                 float* __restrict__ out, int B)
{
    extern __shared__ __align__(16) uint32_t sm[];

    const int tid  = threadIdx.x;
    const int wid  = tid >> 5;
    const int lane = tid & 31;
    const int gid  = lane >> 2;      // 0..7
    const int tig  = lane & 3;       // 0..3
    const int wm   = wid & 3;        // 0..3 : M quarter (32 rows)
    const int wn   = wid >> 2;       // 0..3 : N quarter (64 cols)
    const int m0   = blockIdx.x * 128;
    const int j0   = blockIdx.y * 64;

    float acc[2][8][4];              // [mb][f][c], f = fh*4 + gate
#pragma unroll
    for (int mb = 0; mb < 2; mb++)
#pragma unroll
        for (int f = 0; f < 8; f++)
#pragma unroll
            for (int q = 0; q < 4; q++) acc[mb][f][q] = 0.0f;

    float4 fa, fb[2];

    // ---- LDG one K16 chunk into registers --------------------------------
    auto ldg_chunk = [&](int s) {
        const int kg = s * 16;
        const float* ap; int astr, kl;
        if (kg < 256)      { ap = x;   astr = 256; kl = kg;       }
        else if (kg < 768) { ap = hin; astr = 512; kl = kg - 256; }
        else if (kg < 896) { ap = sp;  astr = 128; kl = kg - 768; }
        else               { ap = tp;  astr = 128; kl = kg - 896; }
        const float* wp;
        if (kg < 256)      wp = Wx + (size_t)kl * 2048;
        else if (kg < 768) wp = Wh + (size_t)kl * 2048;
        else if (kg < 896) wp = Ws + (size_t)kl * 2048;
        else               wp = Wt + (size_t)kl * 2048;

        // A: 128 rows x 16 k = 512 float4, 1 per thread
        {
            const int row = tid >> 2, kq = tid & 3;
            fa = *reinterpret_cast<const float4*>(
                ap + (size_t)(m0 + row) * astr + kl + kq * 4);
        }
        // B: 16 k x 256 n = 1024 float4, 2 per thread; 256B-contiguous runs
#pragma unroll
        for (int i = 0; i < 2; i++) {
            const int v = tid + i * 512;
            const int k = v >> 6, w6 = v & 63;
            const int gate = w6 >> 4, jq = w6 & 15;
            fb[i] = *reinterpret_cast<const float4*>(
                wp + (size_t)k * 2048 + gate * 512 + j0 + jq * 4);
        }
    };

    // ---- STS the registered chunk into stage st --------------------------
    auto sts_chunk = [&](int st) {
        uint32_t* As = sm + st * STAGE_WORDS;
        uint32_t* Bs = As + A_WORDS;
        {
            const int row = tid >> 2, kq = tid & 3;
            *reinterpret_cast<uint4*>(As + row * ASTRIDE + kq * 4) =
                make_uint4(f2tf32(fa.x), f2tf32(fa.y),
                           f2tf32(fa.z), f2tf32(fa.w));
        }
#pragma unroll
        for (int i = 0; i < 2; i++) {
            const int v = tid + i * 512;
            const int k = v >> 6, w6 = v & 63;
            const int gate = w6 >> 4, jq = w6 & 15;
            const int n = (jq >> 2) * 64 + ((jq >> 1) & 1) * 32 + gate * 8 +
                          (jq & 1) * 4;
            *reinterpret_cast<uint4*>(Bs + k * BSTRIDE + n) =
                make_uint4(f2tf32(fb[i].x), f2tf32(fb[i].y),
                           f2tf32(fb[i].z), f2tf32(fb[i].w));
        }
    };

    // ---- compute one K16 chunk from stage st -----------------------------
    auto compute = [&](int st) {
        const uint32_t* As = sm + st * STAGE_WORDS;
        const uint32_t* Bs = As + A_WORDS;
#pragma unroll
        for (int ks = 0; ks < 2; ks++) {
            const int ko = ks * 8;
            uint32_t a[2][4];
#pragma unroll
            for (int mb = 0; mb < 2; mb++) {
                const int rb = wm * 32 + mb * 16;
                a[mb][0] = As[(rb + gid)     * ASTRIDE + ko + tig];
                a[mb][1] = As[(rb + gid + 8) * ASTRIDE + ko + tig];
                a[mb][2] = As[(rb + gid)     * ASTRIDE + ko + tig + 4];
                a[mb][3] = As[(rb + gid + 8) * ASTRIDE + ko + tig + 4];
            }
            uint32_t b[8][2];
#pragma unroll
            for (int f = 0; f < 8; f++) {
                const int nn = wn * 64 + f * 8 + gid;
                b[f][0] = Bs[(ko + tig)     * BSTRIDE + nn];
                b[f][1] = Bs[(ko + tig + 4) * BSTRIDE + nn];
            }
#pragma unroll
            for (int f = 0; f < 8; f++)
#pragma unroll
                for (int mb = 0; mb < 2; mb++)
                    mma_tf32(acc[mb][f], a[mb], b[f][0], b[f][1]);
        }
    };

    // ---- prologue --------------------------------------------------------
    ldg_chunk(0);
    sts_chunk(0);
    ldg_chunk(1);
    if (tid < 256) {   // bias: bhs[gate*64 + jl]
        const int gate = tid >> 6, jl = tid & 63;
        ((float*)(sm + BIAS_OFF))[tid] = bh[gate * 512 + j0 + jl];
    }
    __syncthreads();

    // ---- main loop: 64 chunks --------------------------------------------
#pragma unroll 1
    for (int s = 0; s < 64; s++) {
        if (s + 1 < 64) sts_chunk((s + 1) % 3);   // regs hold chunk s+1
        if (s + 2 < 64) ldg_chunk(s + 2);
        compute(s % 3);
        __syncthreads();
    }

    // ---- epilogue: register-local gates -----------------------------------
    const float* bhs = (const float*)(sm + BIAS_OFF);
#pragma unroll
    for (int mb = 0; mb < 2; mb++) {
#pragma unroll
        for (int fh = 0; fh < 2; fh++) {
#pragma unroll
            for (int q = 0; q < 2; q++) {
                const int jl = wn * 16 + fh * 8 + 2 * tig + q;
                const int j  = j0 + jl;
                const float bi = bhs[0 * 64 + jl];
                const float bf = bhs[1 * 64 + jl];
                const float bo = bhs[2 * 64 + jl];
                const float bc = bhs[3 * 64 + jl];
#pragma unroll
                for (int rh = 0; rh < 2; rh++) {
                    const int row  = m0 + wm * 32 + mb * 16 + gid + 8 * rh;
                    const int cidx = rh * 2 + q;
                    const float pi = acc[mb][fh * 4 + 0][cidx] + bi;
                    const float pf = acc[mb][fh * 4 + 1][cidx] + bf;
                    const float po = acc[mb][fh * 4 + 2][cidx] + bo;
                    const float pc = acc[mb][fh * 4 + 3][cidx] + bc;
                    const float ig = fast_sigmoid(pi);
                    const float fg = fast_sigmoid(pf);
                    const float og = fast_sigmoid(po);
                    const float cg = fast_tanh(pc);
                    const float cn = fg * cin[(size_t)row * 512 + j] + ig * cg;
                    out[(size_t)row * 512 + j] = fast_tanh(og * cn);
                    out[(size_t)B * 512 + (size_t)row * 512 + j] = cn;
                }
            }
        }
    }
}

extern "C" void kernel_launch(void* const* d_in, const int* in_sizes, int n_in,
                              void* d_out, int out_size) {
    const float* x  = (const float*)d_in[0];
    const float* h  = (const float*)d_in[1];
    const float* c  = (const float*)d_in[2];
    const float* sp = (const float*)d_in[3];
    const float* tp = (const float*)d_in[4];
    const float* Wx = (const float*)d_in[5];
    const float* Wh = (const float*)d_in[6];
    const float* bh = (const float*)d_in[7];
    const float* Ws = (const float*)d_in[8];
    const float* Wt = (const float*)d_in[9];
    float* out = (float*)d_out;

    const int B = in_sizes[0] / 256;   // x is [B, 256]
    cudaFuncSetAttribute(lstm_mma_v3,
                         cudaFuncAttributeMaxDynamicSharedMemorySize, SMEM_BYTES);
    dim3 grid(B / 128, 8);
    lstm_mma_v3<<<grid, THREADS, SMEM_BYTES>>>(x, h, c, sp, tp,
                                               Wx, Wh, bh, Ws, Wt, out, B);
}

// round 5
// speedup vs baseline: 1.2323x; 1.1685x over previous
#include <cuda_runtime.h>
#include <cuda_fp16.h>
#include <cstdint>

#define THREADS 512

// ---------------------------------------------------------------------------
// Fused LSTM cell via mma.sync.m16n8k16.f16 (f32 accumulate).
// Rationale: tf32 m16n8k8 is issue-rate-limited (~33% tensor pipe across all
// configs); fp16 k16 halves HMMA instruction count at EQUAL mantissa width
// (10 bits, same as tf32) -> same accuracy, ~2x throughput.
//   preact = [x|h|s|t] @ [Wx;Wh;Ws;Wt] + b   (16384 x 2048, K = 1024)
// CTA tile: 128 rows x 256 preact cols, 16 warps in 4(M)x4(N), warp 32x64.
// K chunk = 32 (2 k16 passes), 3-stage smem pipeline, f16x2 k-pair storage,
// strides 20 words (enumerated conflict-free fragment reads).
// Col mapping n = (jq>>2)*64 + ((jq>>1)&1)*32 + gate*8 + (jq&1)*4 keeps all
// 4 gates of a hidden col in one thread -> register-local epilogue.
// ---------------------------------------------------------------------------

static constexpr int ASTR        = 20;                 // f16x2 words per A row
static constexpr int BSTR        = 20;                 // f16x2 words per B row
static constexpr int A_WORDS     = 128 * ASTR;         // 2560
static constexpr int B_WORDS     = 256 * BSTR;         // 5120
static constexpr int STAGE_WORDS = A_WORDS + B_WORDS;  // 7680
static constexpr int NSTAGE      = 3;
static constexpr int BIAS_OFF    = NSTAGE * STAGE_WORDS;
static constexpr int SMEM_BYTES  = (BIAS_OFF + 256) * 4;   // ~93 KB

__device__ __forceinline__ uint32_t h2pack(float a, float b) {
    __half2 h = __floats2half2_rn(a, b);
    return *reinterpret_cast<uint32_t*>(&h);
}

__device__ __forceinline__ void mma_f16(float* d, const uint32_t* a,
                                        uint32_t b0, uint32_t b1) {
    asm volatile(
        "mma.sync.aligned.m16n8k16.row.col.f32.f16.f16.f32 "
        "{%0,%1,%2,%3}, {%4,%5,%6,%7}, {%8,%9}, {%0,%1,%2,%3};\n"
        : "+f"(d[0]), "+f"(d[1]), "+f"(d[2]), "+f"(d[3])
        : "r"(a[0]), "r"(a[1]), "r"(a[2]), "r"(a[3]), "r"(b0), "r"(b1));
}

__device__ __forceinline__ float fast_sigmoid(float v) {
    return 1.0f / (1.0f + __expf(-v));
}
__device__ __forceinline__ float fast_tanh(float v) {
    float x = fminf(fmaxf(v, -20.0f), 20.0f);
    float e = __expf(2.0f * x);
    return (e - 1.0f) / (e + 1.0f);
}

__global__ __launch_bounds__(THREADS, 1)
void lstm_mma_f16(const float* __restrict__ x,  const float* __restrict__ hin,
                  const float* __restrict__ cin, const float* __restrict__ sp,
                  const float* __restrict__ tp,
                  const float* __restrict__ Wx, const float* __restrict__ Wh,
                  const float* __restrict__ bh, const float* __restrict__ Ws,
                  const float* __restrict__ Wt,
                  float* __restrict__ out, int B)
{
    extern __shared__ __align__(16) uint32_t sm[];

    const int tid  = threadIdx.x;
    const int wid  = tid >> 5;
    const int lane = tid & 31;
    const int gid  = lane >> 2;      // 0..7
    const int tig  = lane & 3;       // 0..3
    const int wm   = wid & 3;        // M quarter (32 rows)
    const int wn   = wid >> 2;       // N quarter (64 cols)
    const int m0   = blockIdx.x * 128;
    const int j0   = blockIdx.y * 64;

    float acc[2][8][4];              // [mb][f][c], f = fh*4 + gate
#pragma unroll
    for (int mb = 0; mb < 2; mb++)
#pragma unroll
        for (int f = 0; f < 8; f++)
#pragma unroll
            for (int q = 0; q < 4; q++) acc[mb][f][q] = 0.0f;

    float4 fa[2], fb[2][2];

    // ---- LDG one K32 chunk into registers --------------------------------
    auto ldg_chunk = [&](int s) {
        const int kg = s * 32;
        const float* ap; int astr, kl;
        if (kg < 256)      { ap = x;   astr = 256; kl = kg;       }
        else if (kg < 768) { ap = hin; astr = 512; kl = kg - 256; }
        else if (kg < 896) { ap = sp;  astr = 128; kl = kg - 768; }
        else               { ap = tp;  astr = 128; kl = kg - 896; }
        const float* wp;
        if (kg < 256)      wp = Wx + (size_t)kl * 2048;
        else if (kg < 768) wp = Wh + (size_t)kl * 2048;
        else if (kg < 896) wp = Ws + (size_t)kl * 2048;
        else               wp = Wt + (size_t)kl * 2048;

        // A: 128 rows x 32 k = 1024 float4, 2 per thread
#pragma unroll
        for (int i = 0; i < 2; i++) {
            const int v = tid + i * 512;
            const int row = v >> 3, kq = v & 7;
            fa[i] = *reinterpret_cast<const float4*>(
                ap + (size_t)(m0 + row) * astr + kl + kq * 4);
        }
        // B: 32 k x 256 n; tasks = 16 kp x 64 n-quads, 2 per thread.
        // Each task loads the SAME 4 cols at k=2kp and k=2kp+1 (pairing for
        // f16x2 along k).
#pragma unroll
        for (int t = 0; t < 2; t++) {
            const int task = tid + t * 512;
            const int kp = task & 15, nq = task >> 4;
            const int gate = nq >> 4, jq = nq & 15;
            const float* base = wp + (size_t)(2 * kp) * 2048 + gate * 512 +
                                j0 + jq * 4;
            fb[t][0] = *reinterpret_cast<const float4*>(base);
            fb[t][1] = *reinterpret_cast<const float4*>(base + 2048);
        }
    };

    // ---- convert + STS the registered chunk into stage st -----------------
    auto sts_chunk = [&](int st) {
        uint32_t* As = sm + st * STAGE_WORDS;
        uint32_t* Bs = As + A_WORDS;
#pragma unroll
        for (int i = 0; i < 2; i++) {
            const int v = tid + i * 512;
            const int row = v >> 3, kq = v & 7;
            *reinterpret_cast<uint2*>(As + row * ASTR + 2 * kq) =
                make_uint2(h2pack(fa[i].x, fa[i].y), h2pack(fa[i].z, fa[i].w));
        }
#pragma unroll
        for (int t = 0; t < 2; t++) {
            const int task = tid + t * 512;
            const int kp = task & 15, nq = task >> 4;
            const int gate = nq >> 4, jq = nq & 15;
            const int n0 = (jq >> 2) * 64 + ((jq >> 1) & 1) * 32 + gate * 8 +
                           (jq & 1) * 4;
            const float* f0 = &fb[t][0].x;
            const float* f1 = &fb[t][1].x;
#pragma unroll
            for (int u = 0; u < 4; u++)
                Bs[(n0 + u) * BSTR + kp] = h2pack(f0[u], f1[u]);
        }
    };

    // ---- compute one K32 chunk from stage st ------------------------------
    auto compute = [&](int st) {
        const uint32_t* As = sm + st * STAGE_WORDS;
        const uint32_t* Bs = As + A_WORDS;
#pragma unroll
        for (int ks = 0; ks < 2; ks++) {
            const int ko = ks * 8;
            uint32_t a[2][4];
#pragma unroll
            for (int mb = 0; mb < 2; mb++) {
                const int rb = wm * 32 + mb * 16;
                const uint32_t* p = As + (rb + gid) * ASTR + ko + tig;
                a[mb][0] = p[0];
                a[mb][1] = p[8 * ASTR];
                a[mb][2] = p[4];
                a[mb][3] = p[8 * ASTR + 4];
            }
            uint32_t b[8][2];
#pragma unroll
            for (int f = 0; f < 8; f++) {
                const uint32_t* p = Bs + (wn * 64 + f * 8 + gid) * BSTR + ko + tig;
                b[f][0] = p[0];
                b[f][1] = p[4];
            }
#pragma unroll
            for (int f = 0; f < 8; f++)
#pragma unroll
                for (int mb = 0; mb < 2; mb++)
                    mma_f16(acc[mb][f], a[mb], b[f][0], b[f][1]);
        }
    };

    // ---- prologue ----------------------------------------------------------
    ldg_chunk(0);
    sts_chunk(0);
    ldg_chunk(1);
    if (tid < 256) {   // bias: bhs[gate*64 + jl]
        const int gate = tid >> 6, jl = tid & 63;
        ((float*)(sm + BIAS_OFF))[tid] = bh[gate * 512 + j0 + jl];
    }
    __syncthreads();

    // ---- main loop: 32 K-chunks -------------------------------------------
#pragma unroll 1
    for (int s = 0; s < 32; s++) {
        if (s + 1 < 32) sts_chunk((s + 1) % 3);   // regs hold chunk s+1
        if (s + 2 < 32) ldg_chunk(s + 2);
        compute(s % 3);
        __syncthreads();
    }

    // ---- epilogue: register-local gates -------------------------------------
    const float* bhs = (const float*)(sm + BIAS_OFF);
#pragma unroll
    for (int mb = 0; mb < 2; mb++) {
#pragma unroll
        for (int fh = 0; fh < 2; fh++) {
#pragma unroll
            for (int q = 0; q < 2; q++) {
                const int jl = wn * 16 + fh * 8 + 2 * tig + q;
                const int j  = j0 + jl;
                const float bi = bhs[0 * 64 + jl];
                const float bf = bhs[1 * 64 + jl];
                const float bo = bhs[2 * 64 + jl];
                const float bc = bhs[3 * 64 + jl];
#pragma unroll
                for (int rh = 0; rh < 2; rh++) {
                    const int row  = m0 + wm * 32 + mb * 16 + gid + 8 * rh;
                    const int cidx = rh * 2 + q;
                    const float pi = acc[mb][fh * 4 + 0][cidx] + bi;
                    const float pf = acc[mb][fh * 4 + 1][cidx] + bf;
                    const float po = acc[mb][fh * 4 + 2][cidx] + bo;
                    const float pc = acc[mb][fh * 4 + 3][cidx] + bc;
                    const float ig = fast_sigmoid(pi);
                    const float fg = fast_sigmoid(pf);
                    const float og = fast_sigmoid(po);
                    const float cg = fast_tanh(pc);
                    const float cn = fg * cin[(size_t)row * 512 + j] + ig * cg;
                    out[(size_t)row * 512 + j] = fast_tanh(og * cn);
                    out[(size_t)B * 512 + (size_t)row * 512 + j] = cn;
                }
            }
        }
    }
}

extern "C" void kernel_launch(void* const* d_in, const int* in_sizes, int n_in,
                              void* d_out, int out_size) {
    const float* x  = (const float*)d_in[0];
    const float* h  = (const float*)d_in[1];
    const float* c  = (const float*)d_in[2];
    const float* sp = (const float*)d_in[3];
    const float* tp = (const float*)d_in[4];
    const float* Wx = (const float*)d_in[5];
    const float* Wh = (const float*)d_in[6];
    const float* bh = (const float*)d_in[7];
    const float* Ws = (const float*)d_in[8];
    const float* Wt = (const float*)d_in[9];
    float* out = (float*)d_out;

    const int B = in_sizes[0] / 256;   // x is [B, 256]
    cudaFuncSetAttribute(lstm_mma_f16,
                         cudaFuncAttributeMaxDynamicSharedMemorySize, SMEM_BYTES);
    dim3 grid(B / 128, 8);
    lstm_mma_f16<<<grid, THREADS, SMEM_BYTES>>>(x, h, c, sp, tp,
                                                Wx, Wh, bh, Ws, Wt, out, B);
}

// round 6
// speedup vs baseline: 2.9581x; 2.4004x over previous
#include <cuda_runtime.h>
#include <cuda_fp16.h>
#include <cstdint>

// ---------------------------------------------------------------------------
// Fused LSTM cell, 3-kernel plan:
//   1) cvtA: [x|h|s|t] f32 -> g_Af16 [16384 x 1024] f16 row-major
//   2) cvtW: [Wx;Wh;Ws;Wt] f32 [1024 x 2048] -> g_Wf16 [2048 x 1024] f16,
//      transposed to n-major with gate-interleave permutation baked in:
//      row r: jb=r>>7, wn=(r>>5)&3, gate=(r>>3)&3, v=r&7
//      original col = gate*512 + jb*32 + wn*8 + v
//   3) lstm_gemm: cp.async 4-stage pipeline + ldmatrix + mma.m16n8k16.f16,
//      CTA 128 rows x 128 preact cols, 8 warps (2M x 4N), warp 64x32,
//      2 CTAs/SM. Epilogue register-local (4 gates per hidden col in one
//      thread), writes h_new then c_new.
// smem rows 64B, seg swizzled by (row>>1): conflict-free for cp.async stores
// and all ldmatrix phases.
// ---------------------------------------------------------------------------

__device__ static __align__(16) uint16_t g_Af16[16384ull * 1024ull];
__device__ static __align__(16) uint16_t g_Wf16[2048ull * 1024ull];

static constexpr int NST      = 4;
static constexpr int STAGE    = 16384;              // A 8KB + B 8KB
static constexpr int BIAS_OFF = NST * STAGE;        // 65536
static constexpr int SMEM     = BIAS_OFF + 512;     // 66048

__device__ __forceinline__ uint32_t s2u(const void* p) {
    uint32_t a;
    asm("{ .reg .u64 t; cvta.to.shared.u64 t, %1; cvt.u32.u64 %0, t; }"
        : "=r"(a) : "l"(p));
    return a;
}
__device__ __forceinline__ void ldsm4(uint32_t& r0, uint32_t& r1,
                                      uint32_t& r2, uint32_t& r3, uint32_t a) {
    asm volatile("ldmatrix.sync.aligned.m8n8.x4.shared.b16 {%0,%1,%2,%3}, [%4];"
                 : "=r"(r0), "=r"(r1), "=r"(r2), "=r"(r3) : "r"(a));
}
__device__ __forceinline__ void mma_f16(float* d, const uint32_t* a,
                                        uint32_t b0, uint32_t b1) {
    asm volatile(
        "mma.sync.aligned.m16n8k16.row.col.f32.f16.f16.f32 "
        "{%0,%1,%2,%3}, {%4,%5,%6,%7}, {%8,%9}, {%0,%1,%2,%3};\n"
        : "+f"(d[0]), "+f"(d[1]), "+f"(d[2]), "+f"(d[3])
        : "r"(a[0]), "r"(a[1]), "r"(a[2]), "r"(a[3]), "r"(b0), "r"(b1));
}
__device__ __forceinline__ float fast_sigmoid(float v) {
    return 1.0f / (1.0f + __expf(-v));
}
__device__ __forceinline__ float fast_tanh(float v) {
    float x = fminf(fmaxf(v, -20.0f), 20.0f);
    float e = __expf(2.0f * x);
    return (e - 1.0f) / (e + 1.0f);
}

// ---- prepass: activations -> f16 -------------------------------------------
__global__ __launch_bounds__(256)
void cvtA(const float* __restrict__ x, const float* __restrict__ h,
          const float* __restrict__ s, const float* __restrict__ t) {
    const int idx = blockIdx.x * 256 + threadIdx.x;
    const int r  = idx >> 7;
    const int k8 = (idx & 127) * 8;
    const float* ap; int astr, kl;
    if (k8 < 256)      { ap = x; astr = 256; kl = k8;       }
    else if (k8 < 768) { ap = h; astr = 512; kl = k8 - 256; }
    else if (k8 < 896) { ap = s; astr = 128; kl = k8 - 768; }
    else               { ap = t; astr = 128; kl = k8 - 896; }
    const float4* src = reinterpret_cast<const float4*>(ap + (size_t)r * astr + kl);
    const float4 f0 = src[0], f1 = src[1];
    __half2 h0 = __floats2half2_rn(f0.x, f0.y);
    __half2 h1 = __floats2half2_rn(f0.z, f0.w);
    __half2 h2 = __floats2half2_rn(f1.x, f1.y);
    __half2 h3 = __floats2half2_rn(f1.z, f1.w);
    uint4 v = make_uint4(*(uint32_t*)&h0, *(uint32_t*)&h1,
                         *(uint32_t*)&h2, *(uint32_t*)&h3);
    *reinterpret_cast<uint4*>(g_Af16 + (size_t)r * 1024 + k8) = v;
}

// ---- prepass: weights -> f16, transposed + permuted -------------------------
__global__ void cvtW(const float* __restrict__ Wx, const float* __restrict__ Wh,
                     const float* __restrict__ Ws, const float* __restrict__ Wt) {
    __shared__ float tile[32][33];
    const int k0 = blockIdx.x * 32;
    const int r0 = blockIdx.y * 32;
    const int tx = threadIdx.x, ty = threadIdx.y;
    const float* wp; int kl;
    if (k0 < 256)      { wp = Wx; kl = k0;       }
    else if (k0 < 768) { wp = Wh; kl = k0 - 256; }
    else if (k0 < 896) { wp = Ws; kl = k0 - 768; }
    else               { wp = Wt; kl = k0 - 896; }
    const int r = r0 + tx;
    const int c = ((r >> 3) & 3) * 512 + (r >> 7) * 32 + ((r >> 5) & 3) * 8 + (r & 7);
    tile[ty][tx] = wp[(size_t)(kl + ty) * 2048 + c];
    __syncthreads();
    g_Wf16[(size_t)(r0 + ty) * 1024 + k0 + tx] =
        __half_as_ushort(__float2half_rn(tile[tx][ty]));
}

// ---- main GEMM + gates ------------------------------------------------------
__global__ __launch_bounds__(256, 2)
void lstm_gemm(const float* __restrict__ cin, const float* __restrict__ bh,
               float* __restrict__ out, int B)
{
    extern __shared__ __align__(1024) char smem[];
    const uint32_t sb = s2u(smem);
    const int tid  = threadIdx.x;
    const int wid  = tid >> 5;
    const int lane = tid & 31;
    const int gid  = lane >> 2;
    const int tig  = lane & 3;
    const int wm   = wid & 1;       // M half  (64 rows)
    const int wn   = wid >> 1;      // N quarter (32 preact cols)
    const int m0   = blockIdx.x * 128;
    const int by   = blockIdx.y;    // 32-hidden-col block

    float acc[4][4][4];
#pragma unroll
    for (int mt = 0; mt < 4; mt++)
#pragma unroll
        for (int nt = 0; nt < 4; nt++)
#pragma unroll
            for (int q = 0; q < 4; q++) acc[mt][nt][q] = 0.0f;

    const uint16_t* Abase = g_Af16 + (size_t)m0 * 1024;
    const uint16_t* Wbase = g_Wf16 + (size_t)by * 128 * 1024;

    auto issue = [&](int s) {
        const uint32_t base = sb + (s & 3) * STAGE;
        const int kg = s * 32;
#pragma unroll
        for (int i = 0; i < 4; i++) {
            const int v   = tid + i * 256;
            const int mat = v >> 9;
            const int row = (v >> 2) & 127;
            const int seg = v & 3;
            const uint32_t dst = base + mat * 8192 + row * 64 +
                                 ((seg ^ (row >> 1)) & 3) * 16;
            const uint16_t* src = (mat ? Wbase : Abase) +
                                  (size_t)row * 1024 + kg + seg * 8;
            asm volatile("cp.async.cg.shared.global [%0], [%1], 16;"
                         :: "r"(dst), "l"(src));
        }
        asm volatile("cp.async.commit_group;" ::: "memory");
    };

    auto compute = [&](int s) {
        const uint32_t ab = sb + (s & 3) * STAGE;
        const uint32_t bb = ab + 8192;
#pragma unroll
        for (int ks = 0; ks < 2; ks++) {
            uint32_t a[4][4];
#pragma unroll
            for (int mt = 0; mt < 4; mt++) {
                const int row = wm * 64 + mt * 16 + (lane & 7) + 8 * ((lane >> 3) & 1);
                const int seg = ks * 2 + ((lane >> 4) & 1);
                const uint32_t addr = ab + row * 64 + ((seg ^ (row >> 1)) & 3) * 16;
                ldsm4(a[mt][0], a[mt][1], a[mt][2], a[mt][3], addr);
            }
            uint32_t b[4][2];
#pragma unroll
            for (int np = 0; np < 2; np++) {
                const int row = wn * 32 + np * 16 + (lane & 7) + 8 * ((lane >> 4) & 1);
                const int seg = ks * 2 + ((lane >> 3) & 1);
                const uint32_t addr = bb + row * 64 + ((seg ^ (row >> 1)) & 3) * 16;
                ldsm4(b[2 * np][0], b[2 * np][1], b[2 * np + 1][0], b[2 * np + 1][1], addr);
            }
#pragma unroll
            for (int mt = 0; mt < 4; mt++)
#pragma unroll
                for (int nt = 0; nt < 4; nt++)
                    mma_f16(acc[mt][nt], a[mt], b[nt][0], b[nt][1]);
        }
    };

    // prologue: bias + first 3 stages in flight
    if (tid < 128) {
        const int g = tid >> 5, jl = tid & 31;
        ((float*)(smem + BIAS_OFF))[tid] = bh[g * 512 + by * 32 + jl];
    }
    issue(0); issue(1); issue(2);

#pragma unroll 1
    for (int s = 0; s < 32; s++) {
        asm volatile("cp.async.wait_group 2;" ::: "memory");
        __syncthreads();
        if (s + 3 < 32) issue(s + 3);
        compute(s);
    }

    // epilogue: register-local gates
    const float* bhs = (const float*)(smem + BIAS_OFF);
    const int jl0 = wn * 8 + 2 * tig;         // hidden col within 32-block
    const int jg  = by * 32 + jl0;
#pragma unroll
    for (int mt = 0; mt < 4; mt++) {
#pragma unroll
        for (int rh = 0; rh < 2; rh++) {
            const int row = m0 + wm * 64 + mt * 16 + gid + 8 * rh;
            const float2 cv = *reinterpret_cast<const float2*>(
                cin + (size_t)row * 512 + jg);
            float hn[2], cn[2];
#pragma unroll
            for (int e = 0; e < 2; e++) {
                const int ci = rh * 2 + e;
                const float pi = acc[mt][0][ci] + bhs[0 * 32 + jl0 + e];
                const float pf = acc[mt][1][ci] + bhs[1 * 32 + jl0 + e];
                const float po = acc[mt][2][ci] + bhs[2 * 32 + jl0 + e];
                const float pc = acc[mt][3][ci] + bhs[3 * 32 + jl0 + e];
                const float ig = fast_sigmoid(pi);
                const float fg = fast_sigmoid(pf);
                const float og = fast_sigmoid(po);
                const float cg = fast_tanh(pc);
                const float c_ = (e ? cv.y : cv.x);
                cn[e] = fg * c_ + ig * cg;
                hn[e] = fast_tanh(og * cn[e]);
            }
            *reinterpret_cast<float2*>(out + (size_t)row * 512 + jg) =
                make_float2(hn[0], hn[1]);
            *reinterpret_cast<float2*>(out + (size_t)B * 512 +
                                       (size_t)row * 512 + jg) =
                make_float2(cn[0], cn[1]);
        }
    }
}

extern "C" void kernel_launch(void* const* d_in, const int* in_sizes, int n_in,
                              void* d_out, int out_size) {
    const float* x  = (const float*)d_in[0];
    const float* h  = (const float*)d_in[1];
    const float* c  = (const float*)d_in[2];
    const float* sp = (const float*)d_in[3];
    const float* tp = (const float*)d_in[4];
    const float* Wx = (const float*)d_in[5];
    const float* Wh = (const float*)d_in[6];
    const float* bh = (const float*)d_in[7];
    const float* Ws = (const float*)d_in[8];
    const float* Wt = (const float*)d_in[9];
    float* out = (float*)d_out;

    const int B = in_sizes[0] / 256;   // x is [B, 256]

    cvtA<<<(B * 128) / 256, 256>>>(x, h, sp, tp);
    cvtW<<<dim3(32, 64), dim3(32, 32)>>>(Wx, Wh, Ws, Wt);

    static int smem_set = 0;
    if (!smem_set) {
        cudaFuncSetAttribute(lstm_gemm,
                             cudaFuncAttributeMaxDynamicSharedMemorySize, SMEM);
        smem_set = 1;
    }
    lstm_gemm<<<dim3(B / 128, 16), 256, SMEM>>>(c, bh, out, B);
}

// round 7
// speedup vs baseline: 3.2638x; 1.1034x over previous
#include <cuda_runtime.h>
#include <cuda_fp16.h>
#include <cstdint>

// ---------------------------------------------------------------------------
// Fused LSTM cell, 2-kernel plan:
//   1) prep: (a) [x|h|s|t] f32 -> g_Af16 [16384 x 1024] f16 row-major
//            (b) [Wx;Wh;Ws;Wt] f32 [1024 x 2048] -> g_Wf16 [2048 x 1024] f16,
//                transposed to n-major with gate-interleave permutation:
//                row r -> original col ((r>>3)&3)*512 + (r>>7)*32 + ((r>>5)&3)*8 + (r&7)
//   2) lstm_gemm: cp.async 3-stage K64 pipeline + ldmatrix + mma.m16n8k16.f16,
//      CTA 128 rows x 128 preact cols, 8 warps (2M x 4N), warp 64x32,
//      2 CTAs/SM. Register-local gate epilogue.
// smem rows 128B, 16B segs swizzled seg^(row&7): conflict-free for cp.async
// stores and all ldmatrix phases.
// ---------------------------------------------------------------------------

__device__ static __align__(16) uint16_t g_Af16[16384ull * 1024ull];
__device__ static __align__(16) uint16_t g_Wf16[2048ull * 1024ull];

static constexpr int NST      = 3;
static constexpr int STAGE    = 32768;              // A 16KB + B 16KB
static constexpr int BIAS_OFF = NST * STAGE;        // 98304
static constexpr int SMEM     = BIAS_OFF + 512;     // 98816

__device__ __forceinline__ uint32_t s2u(const void* p) {
    uint32_t a;
    asm("{ .reg .u64 t; cvta.to.shared.u64 t, %1; cvt.u32.u64 %0, t; }"
        : "=r"(a) : "l"(p));
    return a;
}
__device__ __forceinline__ void ldsm4(uint32_t& r0, uint32_t& r1,
                                      uint32_t& r2, uint32_t& r3, uint32_t a) {
    asm volatile("ldmatrix.sync.aligned.m8n8.x4.shared.b16 {%0,%1,%2,%3}, [%4];"
                 : "=r"(r0), "=r"(r1), "=r"(r2), "=r"(r3) : "r"(a));
}
__device__ __forceinline__ void mma_f16(float* d, const uint32_t* a,
                                        uint32_t b0, uint32_t b1) {
    asm volatile(
        "mma.sync.aligned.m16n8k16.row.col.f32.f16.f16.f32 "
        "{%0,%1,%2,%3}, {%4,%5,%6,%7}, {%8,%9}, {%0,%1,%2,%3};\n"
        : "+f"(d[0]), "+f"(d[1]), "+f"(d[2]), "+f"(d[3])
        : "r"(a[0]), "r"(a[1]), "r"(a[2]), "r"(a[3]), "r"(b0), "r"(b1));
}
__device__ __forceinline__ float fast_sigmoid(float v) {
    return 1.0f / (1.0f + __expf(-v));
}
__device__ __forceinline__ float fast_tanh(float v) {
    float x = fminf(fmaxf(v, -20.0f), 20.0f);
    float e = __expf(2.0f * x);
    return (e - 1.0f) / (e + 1.0f);
}

// ---- prepass: activations + weights -> f16 scratch -------------------------
__global__ __launch_bounds__(256)
void prep(const float* __restrict__ x, const float* __restrict__ h,
          const float* __restrict__ s, const float* __restrict__ t,
          const float* __restrict__ Wx, const float* __restrict__ Wh,
          const float* __restrict__ Ws, const float* __restrict__ Wt,
          int ablocks) {
    const int tid = threadIdx.x;
    if ((int)blockIdx.x < ablocks) {
        const int idx = blockIdx.x * 256 + tid;
        const int r  = idx >> 7;
        const int k8 = (idx & 127) * 8;
        const float* ap; int astr, kl;
        if (k8 < 256)      { ap = x; astr = 256; kl = k8;       }
        else if (k8 < 768) { ap = h; astr = 512; kl = k8 - 256; }
        else if (k8 < 896) { ap = s; astr = 128; kl = k8 - 768; }
        else               { ap = t; astr = 128; kl = k8 - 896; }
        const float4* src = reinterpret_cast<const float4*>(
            ap + (size_t)r * astr + kl);
        const float4 f0 = src[0], f1 = src[1];
        __half2 h0 = __floats2half2_rn(f0.x, f0.y);
        __half2 h1 = __floats2half2_rn(f0.z, f0.w);
        __half2 h2 = __floats2half2_rn(f1.x, f1.y);
        __half2 h3 = __floats2half2_rn(f1.z, f1.w);
        uint4 v = make_uint4(*(uint32_t*)&h0, *(uint32_t*)&h1,
                             *(uint32_t*)&h2, *(uint32_t*)&h3);
        *reinterpret_cast<uint4*>(g_Af16 + (size_t)r * 1024 + k8) = v;
    } else {
        __shared__ float tile[32][33];
        const int wb = blockIdx.x - ablocks;      // 0..2047
        const int k0 = (wb & 31) * 32;
        const int r0 = (wb >> 5) * 32;
        const float* wp; int kl;
        if (k0 < 256)      { wp = Wx; kl = k0;       }
        else if (k0 < 768) { wp = Wh; kl = k0 - 256; }
        else if (k0 < 896) { wp = Ws; kl = k0 - 768; }
        else               { wp = Wt; kl = k0 - 896; }
        const int tx = tid & 31, ty = tid >> 5;
        const int r = r0 + tx;
        const int c = ((r >> 3) & 3) * 512 + (r >> 7) * 32 +
                      ((r >> 5) & 3) * 8 + (r & 7);
#pragma unroll
        for (int i = 0; i < 4; i++) {
            const int ky = ty + 8 * i;
            tile[tx][ky] = wp[(size_t)(kl + ky) * 2048 + c];
        }
        __syncthreads();
#pragma unroll
        for (int i = 0; i < 4; i++) {
            const int ky = ty + 8 * i;
            g_Wf16[(size_t)(r0 + ky) * 1024 + k0 + tx] =
                __half_as_ushort(__float2half_rn(tile[ky][tx]));
        }
    }
}

// ---- main GEMM + gates ------------------------------------------------------
__global__ __launch_bounds__(256, 2)
void lstm_gemm(const float* __restrict__ cin, const float* __restrict__ bh,
               float* __restrict__ out, int B)
{
    extern __shared__ __align__(1024) char smem[];
    const uint32_t sb = s2u(smem);
    const int tid  = threadIdx.x;
    const int wid  = tid >> 5;
    const int lane = tid & 31;
    const int gid  = lane >> 2;
    const int tig  = lane & 3;
    const int wm   = wid & 1;       // M half  (64 rows)
    const int wn   = wid >> 1;      // N quarter (32 preact cols)
    const int m0   = blockIdx.x * 128;
    const int by   = blockIdx.y;    // 32-hidden-col block

    float acc[4][4][4];
#pragma unroll
    for (int mt = 0; mt < 4; mt++)
#pragma unroll
        for (int nt = 0; nt < 4; nt++)
#pragma unroll
            for (int q = 0; q < 4; q++) acc[mt][nt][q] = 0.0f;

    const uint16_t* Abase = g_Af16 + (size_t)m0 * 1024;
    const uint16_t* Wbase = g_Wf16 + (size_t)by * 128 * 1024;

    auto issue = [&](int s) {
        const uint32_t base = sb + (s % NST) * STAGE;
        const int kg = s * 64;
#pragma unroll
        for (int i = 0; i < 8; i++) {
            const int v   = tid + i * 256;
            const int mat = v >> 10;
            const int row = (v >> 3) & 127;
            const int seg = v & 7;
            const uint32_t dst = base + mat * 16384 + row * 128 +
                                 (seg ^ (row & 7)) * 16;
            const uint16_t* src = (mat ? Wbase : Abase) +
                                  (size_t)row * 1024 + kg + seg * 8;
            asm volatile("cp.async.cg.shared.global [%0], [%1], 16;"
                         :: "r"(dst), "l"(src));
        }
        asm volatile("cp.async.commit_group;" ::: "memory");
    };

    auto compute = [&](int s) {
        const uint32_t ab = sb + (s % NST) * STAGE;
        const uint32_t bb = ab + 16384;
#pragma unroll
        for (int ks = 0; ks < 4; ks++) {
            uint32_t a[4][4];
#pragma unroll
            for (int mt = 0; mt < 4; mt++) {
                const int row = wm * 64 + mt * 16 + (lane & 7) +
                                8 * ((lane >> 3) & 1);
                const int seg = 2 * ks + ((lane >> 4) & 1);
                const uint32_t addr = ab + row * 128 + (seg ^ (row & 7)) * 16;
                ldsm4(a[mt][0], a[mt][1], a[mt][2], a[mt][3], addr);
            }
            uint32_t b[4][2];
#pragma unroll
            for (int np = 0; np < 2; np++) {
                const int row = wn * 32 + np * 16 + (lane & 7) +
                                8 * ((lane >> 4) & 1);
                const int seg = 2 * ks + ((lane >> 3) & 1);
                const uint32_t addr = bb + row * 128 + (seg ^ (row & 7)) * 16;
                ldsm4(b[2 * np][0], b[2 * np][1],
                      b[2 * np + 1][0], b[2 * np + 1][1], addr);
            }
#pragma unroll
            for (int mt = 0; mt < 4; mt++)
#pragma unroll
                for (int nt = 0; nt < 4; nt++)
                    mma_f16(acc[mt][nt], a[mt], b[nt][0], b[nt][1]);
        }
    };

    // prologue: bias + 2 stages in flight
    if (tid < 128) {
        const int g = tid >> 5, jl = tid & 31;
        ((float*)(smem + BIAS_OFF))[tid] = bh[g * 512 + by * 32 + jl];
    }
    issue(0); issue(1);

#pragma unroll 1
    for (int s = 0; s < 16; s++) {
        if (s + 2 < 16)
            asm volatile("cp.async.wait_group 1;" ::: "memory");
        else
            asm volatile("cp.async.wait_group 0;" ::: "memory");
        __syncthreads();
        if (s + 2 < 16) issue(s + 2);
        compute(s);
    }

    // epilogue: register-local gates
    const float* bhs = (const float*)(smem + BIAS_OFF);
    const int jl0 = wn * 8 + 2 * tig;         // hidden col within 32-block
    const int jg  = by * 32 + jl0;
#pragma unroll
    for (int mt = 0; mt < 4; mt++) {
#pragma unroll
        for (int rh = 0; rh < 2; rh++) {
            const int row = m0 + wm * 64 + mt * 16 + gid + 8 * rh;
            const float2 cv = *reinterpret_cast<const float2*>(
                cin + (size_t)row * 512 + jg);
            float hn[2], cn[2];
#pragma unroll
            for (int e = 0; e < 2; e++) {
                const int ci = rh * 2 + e;
                const float pi = acc[mt][0][ci] + bhs[0 * 32 + jl0 + e];
                const float pf = acc[mt][1][ci] + bhs[1 * 32 + jl0 + e];
                const float po = acc[mt][2][ci] + bhs[2 * 32 + jl0 + e];
                const float pc = acc[mt][3][ci] + bhs[3 * 32 + jl0 + e];
                const float ig = fast_sigmoid(pi);
                const float fg = fast_sigmoid(pf);
                const float og = fast_sigmoid(po);
                const float cg = fast_tanh(pc);
                const float c_ = (e ? cv.y : cv.x);
                cn[e] = fg * c_ + ig * cg;
                hn[e] = fast_tanh(og * cn[e]);
            }
            *reinterpret_cast<float2*>(out + (size_t)row * 512 + jg) =
                make_float2(hn[0], hn[1]);
            *reinterpret_cast<float2*>(out + (size_t)B * 512 +
                                       (size_t)row * 512 + jg) =
                make_float2(cn[0], cn[1]);
        }
    }
}

extern "C" void kernel_launch(void* const* d_in, const int* in_sizes, int n_in,
                              void* d_out, int out_size) {
    const float* x  = (const float*)d_in[0];
    const float* h  = (const float*)d_in[1];
    const float* c  = (const float*)d_in[2];
    const float* sp = (const float*)d_in[3];
    const float* tp = (const float*)d_in[4];
    const float* Wx = (const float*)d_in[5];
    const float* Wh = (const float*)d_in[6];
    const float* bh = (const float*)d_in[7];
    const float* Ws = (const float*)d_in[8];
    const float* Wt = (const float*)d_in[9];
    float* out = (float*)d_out;

    const int B = in_sizes[0] / 256;   // x is [B, 256]
    const int ablocks = (B * 128) / 256;

    prep<<<ablocks + 2048, 256>>>(x, h, sp, tp, Wx, Wh, Ws, Wt, ablocks);

    static int smem_set = 0;
    if (!smem_set) {
        cudaFuncSetAttribute(lstm_gemm,
                             cudaFuncAttributeMaxDynamicSharedMemorySize, SMEM);
        smem_set = 1;
    }
    lstm_gemm<<<dim3(B / 128, 16), 256, SMEM>>>(c, bh, out, B);
}

// round 9
// speedup vs baseline: 3.4906x; 1.0695x over previous
#include <cuda_runtime.h>
#include <cuda_fp16.h>
#include <cstdint>

// ---------------------------------------------------------------------------
// Fused LSTM cell, 2-kernel plan:
//   1) prep: (a) [x|h|s|t] f32 -> g_Af16 [16384 x 1024] f16 row-major
//            (b) W f32 [1024 x 2048] -> g_Wf16 [2048 x 1024] f16 transposed,
//                gate-interleave permutation baked in.
//   2) lstm_gemm: cp.async 3-stage K64 pipeline, mbarrier producer/consumer
//      protocol (NO __syncthreads in mainloop -> warps drift, tensor gaps
//      overlap), ldmatrix + mma.m16n8k16.f16, CTA 128x128, 8 warps (2Mx4N),
//      2 CTAs/SM. Register-local gate epilogue, per-warp retirement.
// R9 fix vs R8: cp.async.mbarrier.arrive requires .noinc (default variant
// pre-increments the pending count -> count-neutral -> R8 deadlock).
// smem rows 128B, 16B segs swizzled seg^(row&7): conflict-free everywhere.
// ---------------------------------------------------------------------------

__device__ static __align__(16) uint16_t g_Af16[16384ull * 1024ull];
__device__ static __align__(16) uint16_t g_Wf16[2048ull * 1024ull];

static constexpr int NST      = 3;
static constexpr int STAGE    = 32768;              // A 16KB + B 16KB
static constexpr int BIAS_OFF = NST * STAGE;        // 98304
static constexpr int MBAR_OFF = BIAS_OFF + 512;     // 98816: full[3], empty[3]
static constexpr int SMEM     = MBAR_OFF + 64;      // 98880

__device__ __forceinline__ uint32_t s2u(const void* p) {
    uint32_t a;
    asm("{ .reg .u64 t; cvta.to.shared.u64 t, %1; cvt.u32.u64 %0, t; }"
        : "=r"(a) : "l"(p));
    return a;
}
__device__ __forceinline__ void mbar_init(uint32_t mb, uint32_t cnt) {
    asm volatile("mbarrier.init.shared.b64 [%0], %1;" :: "r"(mb), "r"(cnt)
                 : "memory");
}
__device__ __forceinline__ void mbar_arrive(uint32_t mb) {
    asm volatile("mbarrier.arrive.shared.b64 _, [%0];" :: "r"(mb) : "memory");
}
__device__ __forceinline__ void cp_arrive_noinc(uint32_t mb) {
    asm volatile("cp.async.mbarrier.arrive.noinc.shared.b64 [%0];" :: "r"(mb)
                 : "memory");
}
__device__ __forceinline__ void mbar_wait(uint32_t mb, uint32_t parity) {
    asm volatile(
        "{\n\t.reg .pred P;\n\t"
        "WL_%=:\n\t"
        "mbarrier.try_wait.parity.acquire.cta.shared::cta.b64 P, [%0], %1, 0x989680;\n\t"
        "@P bra WD_%=;\n\t"
        "bra WL_%=;\n\t"
        "WD_%=:\n\t}"
        :: "r"(mb), "r"(parity) : "memory");
}
__device__ __forceinline__ void ldsm4(uint32_t& r0, uint32_t& r1,
                                      uint32_t& r2, uint32_t& r3, uint32_t a) {
    asm volatile("ldmatrix.sync.aligned.m8n8.x4.shared.b16 {%0,%1,%2,%3}, [%4];"
                 : "=r"(r0), "=r"(r1), "=r"(r2), "=r"(r3) : "r"(a));
}
__device__ __forceinline__ void mma_f16(float* d, const uint32_t* a,
                                        uint32_t b0, uint32_t b1) {
    asm volatile(
        "mma.sync.aligned.m16n8k16.row.col.f32.f16.f16.f32 "
        "{%0,%1,%2,%3}, {%4,%5,%6,%7}, {%8,%9}, {%0,%1,%2,%3};\n"
        : "+f"(d[0]), "+f"(d[1]), "+f"(d[2]), "+f"(d[3])
        : "r"(a[0]), "r"(a[1]), "r"(a[2]), "r"(a[3]), "r"(b0), "r"(b1));
}
__device__ __forceinline__ float fast_sigmoid(float v) {
    return 1.0f / (1.0f + __expf(-v));
}
__device__ __forceinline__ float fast_tanh(float v) {
    float x = fminf(fmaxf(v, -20.0f), 20.0f);
    float e = __expf(2.0f * x);
    return (e - 1.0f) / (e + 1.0f);
}

// ---- prepass: activations + weights -> f16 scratch -------------------------
__global__ __launch_bounds__(256)
void prep(const float* __restrict__ x, const float* __restrict__ h,
          const float* __restrict__ s, const float* __restrict__ t,
          const float* __restrict__ Wx, const float* __restrict__ Wh,
          const float* __restrict__ Ws, const float* __restrict__ Wt,
          int ablocks) {
    const int tid = threadIdx.x;
    if ((int)blockIdx.x < ablocks) {
        const int idx = blockIdx.x * 256 + tid;
        const int r  = idx >> 7;
        const int k8 = (idx & 127) * 8;
        const float* ap; int astr, kl;
        if (k8 < 256)      { ap = x; astr = 256; kl = k8;       }
        else if (k8 < 768) { ap = h; astr = 512; kl = k8 - 256; }
        else if (k8 < 896) { ap = s; astr = 128; kl = k8 - 768; }
        else               { ap = t; astr = 128; kl = k8 - 896; }
        const float4* src = reinterpret_cast<const float4*>(
            ap + (size_t)r * astr + kl);
        const float4 f0 = src[0], f1 = src[1];
        __half2 h0 = __floats2half2_rn(f0.x, f0.y);
        __half2 h1 = __floats2half2_rn(f0.z, f0.w);
        __half2 h2 = __floats2half2_rn(f1.x, f1.y);
        __half2 h3 = __floats2half2_rn(f1.z, f1.w);
        uint4 v = make_uint4(*(uint32_t*)&h0, *(uint32_t*)&h1,
                             *(uint32_t*)&h2, *(uint32_t*)&h3);
        *reinterpret_cast<uint4*>(g_Af16 + (size_t)r * 1024 + k8) = v;
    } else {
        __shared__ float tile[32][33];
        const int wb = blockIdx.x - ablocks;      // 0..2047
        const int k0 = (wb & 31) * 32;
        const int r0 = (wb >> 5) * 32;
        const float* wp; int kl;
        if (k0 < 256)      { wp = Wx; kl = k0;       }
        else if (k0 < 768) { wp = Wh; kl = k0 - 256; }
        else if (k0 < 896) { wp = Ws; kl = k0 - 768; }
        else               { wp = Wt; kl = k0 - 896; }
        const int tx = tid & 31, ty = tid >> 5;
        const int r = r0 + tx;
        const int c = ((r >> 3) & 3) * 512 + (r >> 7) * 32 +
                      ((r >> 5) & 3) * 8 + (r & 7);
#pragma unroll
        for (int i = 0; i < 4; i++) {
            const int ky = ty + 8 * i;
            tile[tx][ky] = wp[(size_t)(kl + ky) * 2048 + c];
        }
        __syncthreads();
#pragma unroll
        for (int i = 0; i < 4; i++) {
            const int ky = ty + 8 * i;
            g_Wf16[(size_t)(r0 + ky) * 1024 + k0 + tx] =
                __half_as_ushort(__float2half_rn(tile[ky][tx]));
        }
    }
}

// ---- main GEMM + gates ------------------------------------------------------
__global__ __launch_bounds__(256, 2)
void lstm_gemm(const float* __restrict__ cin, const float* __restrict__ bh,
               float* __restrict__ out, int B)
{
    extern __shared__ __align__(1024) char smem[];
    const uint32_t sb = s2u(smem);
    const uint32_t mb_full  = sb + MBAR_OFF;        // 3 x 8B
    const uint32_t mb_empty = sb + MBAR_OFF + 24;   // 3 x 8B
    const int tid  = threadIdx.x;
    const int wid  = tid >> 5;
    const int lane = tid & 31;
    const int gid  = lane >> 2;
    const int tig  = lane & 3;
    const int wm   = wid & 1;       // M half  (64 rows)
    const int wn   = wid >> 1;      // N quarter (32 preact cols)
    const int m0   = blockIdx.x * 128;
    const int by   = blockIdx.y;    // 32-hidden-col block

    float acc[4][4][4];
#pragma unroll
    for (int mt = 0; mt < 4; mt++)
#pragma unroll
        for (int nt = 0; nt < 4; nt++)
#pragma unroll
            for (int q = 0; q < 4; q++) acc[mt][nt][q] = 0.0f;

    const uint16_t* Abase = g_Af16 + (size_t)m0 * 1024;
    const uint16_t* Wbase = g_Wf16 + (size_t)by * 128 * 1024;

    // issue chunk q into stage stq; cp.async completion -> full[stq] arrival
    auto issue = [&](int q, int stq) {
        const uint32_t base = sb + stq * STAGE;
        const int kg = q * 64;
#pragma unroll
        for (int i = 0; i < 8; i++) {
            const int v   = tid + i * 256;
            const int mat = v >> 10;
            const int row = (v >> 3) & 127;
            const int seg = v & 7;
            const uint32_t dst = base + mat * 16384 + row * 128 +
                                 (seg ^ (row & 7)) * 16;
            const uint16_t* src = (mat ? Wbase : Abase) +
                                  (size_t)row * 1024 + kg + seg * 8;
            asm volatile("cp.async.cg.shared.global [%0], [%1], 16;"
                         :: "r"(dst), "l"(src));
        }
        cp_arrive_noinc(mb_full + 8 * stq);
    };

    auto compute = [&](int st) {
        const uint32_t ab = sb + st * STAGE;
        const uint32_t bb = ab + 16384;
#pragma unroll
        for (int ks = 0; ks < 4; ks++) {
            uint32_t a[4][4];
#pragma unroll
            for (int mt = 0; mt < 4; mt++) {
                const int row = wm * 64 + mt * 16 + (lane & 7) +
                                8 * ((lane >> 3) & 1);
                const int seg = 2 * ks + ((lane >> 4) & 1);
                const uint32_t addr = ab + row * 128 + (seg ^ (row & 7)) * 16;
                ldsm4(a[mt][0], a[mt][1], a[mt][2], a[mt][3], addr);
            }
            uint32_t b[4][2];
#pragma unroll
            for (int np = 0; np < 2; np++) {
                const int row = wn * 32 + np * 16 + (lane & 7) +
                                8 * ((lane >> 4) & 1);
                const int seg = 2 * ks + ((lane >> 3) & 1);
                const uint32_t addr = bb + row * 128 + (seg ^ (row & 7)) * 16;
                ldsm4(b[2 * np][0], b[2 * np][1],
                      b[2 * np + 1][0], b[2 * np + 1][1], addr);
            }
#pragma unroll
            for (int mt = 0; mt < 4; mt++)
#pragma unroll
                for (int nt = 0; nt < 4; nt++)
                    mma_f16(acc[mt][nt], a[mt], b[nt][0], b[nt][1]);
        }
    };

    // prologue: bias, mbarrier init, 2 stages in flight
    if (tid < 128) {
        const int g = tid >> 5, jl = tid & 31;
        ((float*)(smem + BIAS_OFF))[tid] = bh[g * 512 + by * 32 + jl];
    }
    if (tid == 0) {
#pragma unroll
        for (int i = 0; i < NST; i++) {
            mbar_init(mb_full + 8 * i, 256);
            mbar_init(mb_empty + 8 * i, 256);
        }
    }
    __syncthreads();
    issue(0, 0);
    issue(1, 1);

    // mainloop: wait full -> compute -> arrive empty -> wait empty -> issue
#pragma unroll 1
    for (int s = 0; s < 16; s++) {
        const int d  = (s * 11) >> 5;        // s / 3 for s < 18
        const int st = s - 3 * d;
        mbar_wait(mb_full + 8 * st, d & 1);
        compute(st);
        mbar_arrive(mb_empty + 8 * st);
        const int q = s + 2;
        if (q < 16) {
            const int dq  = (q * 11) >> 5;
            const int stq = q - 3 * dq;
            if (q >= NST)
                mbar_wait(mb_empty + 8 * stq, (dq - 1) & 1);
            issue(q, stq);
        }
    }

    // epilogue: register-local gates, per-warp retirement (no final sync)
    const float* bhs = (const float*)(smem + BIAS_OFF);
    const int jl0 = wn * 8 + 2 * tig;         // hidden col within 32-block
    const int jg  = by * 32 + jl0;
#pragma unroll
    for (int mt = 0; mt < 4; mt++) {
#pragma unroll
        for (int rh = 0; rh < 2; rh++) {
            const int row = m0 + wm * 64 + mt * 16 + gid + 8 * rh;
            const float2 cv = *reinterpret_cast<const float2*>(
                cin + (size_t)row * 512 + jg);
            float hn[2], cn[2];
#pragma unroll
            for (int e = 0; e < 2; e++) {
                const int ci = rh * 2 + e;
                const float pi = acc[mt][0][ci] + bhs[0 * 32 + jl0 + e];
                const float pf = acc[mt][1][ci] + bhs[1 * 32 + jl0 + e];
                const float po = acc[mt][2][ci] + bhs[2 * 32 + jl0 + e];
                const float pc = acc[mt][3][ci] + bhs[3 * 32 + jl0 + e];
                const float ig = fast_sigmoid(pi);
                const float fg = fast_sigmoid(pf);
                const float og = fast_sigmoid(po);
                const float cg = fast_tanh(pc);
                const float c_ = (e ? cv.y : cv.x);
                cn[e] = fg * c_ + ig * cg;
                hn[e] = fast_tanh(og * cn[e]);
            }
            *reinterpret_cast<float2*>(out + (size_t)row * 512 + jg) =
                make_float2(hn[0], hn[1]);
            *reinterpret_cast<float2*>(out + (size_t)B * 512 +
                                       (size_t)row * 512 + jg) =
                make_float2(cn[0], cn[1]);
        }
    }
}

extern "C" void kernel_launch(void* const* d_in, const int* in_sizes, int n_in,
                              void* d_out, int out_size) {
    const float* x  = (const float*)d_in[0];
    const float* h  = (const float*)d_in[1];
    const float* c  = (const float*)d_in[2];
    const float* sp = (const float*)d_in[3];
    const float* tp = (const float*)d_in[4];
    const float* Wx = (const float*)d_in[5];
    const float* Wh = (const float*)d_in[6];
    const float* bh = (const float*)d_in[7];
    const float* Ws = (const float*)d_in[8];
    const float* Wt = (const float*)d_in[9];
    float* out = (float*)d_out;

    const int B = in_sizes[0] / 256;   // x is [B, 256]
    const int ablocks = (B * 128) / 256;

    prep<<<ablocks + 2048, 256>>>(x, h, sp, tp, Wx, Wh, Ws, Wt, ablocks);

    static int smem_set = 0;
    if (!smem_set) {
        cudaFuncSetAttribute(lstm_gemm,
                             cudaFuncAttributeMaxDynamicSharedMemorySize, SMEM);
        smem_set = 1;
    }
    lstm_gemm<<<dim3(B / 128, 16), 256, SMEM>>>(c, bh, out, B);
}

// round 10
// speedup vs baseline: 3.9490x; 1.1313x over previous
#include <cuda_runtime.h>
#include <cuda_fp16.h>
#include <cstdint>

// ---------------------------------------------------------------------------
// Fused LSTM cell, 2-kernel plan (R10):
//   1) prep: activations -> g_Af16 [16384x1024]; W -> g_Wf16 [2048x1024]
//      transposed + gate-interleave permuted.
//   2) lstm_gemm: cp.async 3-stage K64 mbarrier pipeline, ldmatrix +
//      mma.m16n8k16.f16, CTA 128x128, 8 warps (2Mx4N), 2 CTAs/SM.
// R10 vs R9:
//   - empty mbarriers: per-warp arrivals (init 8, lane0 arrives) -> 32x less
//     mbarrier traffic
//   - wait_empty + issue moved INSIDE compute (after ks=0) -> cp.async issue
//     and TRYWAIT overlap the MMA stream
//   - epilogue uses tanh.approx.f32 (sigmoid via tanh identity) -> half MUFU
// ---------------------------------------------------------------------------

__device__ static __align__(16) uint16_t g_Af16[16384ull * 1024ull];
__device__ static __align__(16) uint16_t g_Wf16[2048ull * 1024ull];

static constexpr int NST      = 3;
static constexpr int STAGE    = 32768;              // A 16KB + B 16KB
static constexpr int BIAS_OFF = NST * STAGE;        // 98304
static constexpr int MBAR_OFF = BIAS_OFF + 512;     // 98816: full[3], empty[3]
static constexpr int SMEM     = MBAR_OFF + 64;      // 98880

__device__ __forceinline__ uint32_t s2u(const void* p) {
    uint32_t a;
    asm("{ .reg .u64 t; cvta.to.shared.u64 t, %1; cvt.u32.u64 %0, t; }"
        : "=r"(a) : "l"(p));
    return a;
}
__device__ __forceinline__ void mbar_init(uint32_t mb, uint32_t cnt) {
    asm volatile("mbarrier.init.shared.b64 [%0], %1;" :: "r"(mb), "r"(cnt)
                 : "memory");
}
__device__ __forceinline__ void mbar_arrive(uint32_t mb) {
    asm volatile("mbarrier.arrive.shared.b64 _, [%0];" :: "r"(mb) : "memory");
}
__device__ __forceinline__ void cp_arrive_noinc(uint32_t mb) {
    asm volatile("cp.async.mbarrier.arrive.noinc.shared.b64 [%0];" :: "r"(mb)
                 : "memory");
}
__device__ __forceinline__ void mbar_wait(uint32_t mb, uint32_t parity) {
    asm volatile(
        "{\n\t.reg .pred P;\n\t"
        "WL_%=:\n\t"
        "mbarrier.try_wait.parity.acquire.cta.shared::cta.b64 P, [%0], %1, 0x989680;\n\t"
        "@P bra WD_%=;\n\t"
        "bra WL_%=;\n\t"
        "WD_%=:\n\t}"
        :: "r"(mb), "r"(parity) : "memory");
}
__device__ __forceinline__ void ldsm4(uint32_t& r0, uint32_t& r1,
                                      uint32_t& r2, uint32_t& r3, uint32_t a) {
    asm volatile("ldmatrix.sync.aligned.m8n8.x4.shared.b16 {%0,%1,%2,%3}, [%4];"
                 : "=r"(r0), "=r"(r1), "=r"(r2), "=r"(r3) : "r"(a));
}
__device__ __forceinline__ void mma_f16(float* d, const uint32_t* a,
                                        uint32_t b0, uint32_t b1) {
    asm volatile(
        "mma.sync.aligned.m16n8k16.row.col.f32.f16.f16.f32 "
        "{%0,%1,%2,%3}, {%4,%5,%6,%7}, {%8,%9}, {%0,%1,%2,%3};\n"
        : "+f"(d[0]), "+f"(d[1]), "+f"(d[2]), "+f"(d[3])
        : "r"(a[0]), "r"(a[1]), "r"(a[2]), "r"(a[3]), "r"(b0), "r"(b1));
}
__device__ __forceinline__ float tanh_a(float x) {
    float y;
    asm("tanh.approx.f32 %0, %1;" : "=f"(y) : "f"(x));
    return y;
}
__device__ __forceinline__ float sigm_a(float x) {
    return fmaf(tanh_a(0.5f * x), 0.5f, 0.5f);
}

// ---- prepass: activations + weights -> f16 scratch -------------------------
__global__ __launch_bounds__(256)
void prep(const float* __restrict__ x, const float* __restrict__ h,
          const float* __restrict__ s, const float* __restrict__ t,
          const float* __restrict__ Wx, const float* __restrict__ Wh,
          const float* __restrict__ Ws, const float* __restrict__ Wt,
          int ablocks) {
    const int tid = threadIdx.x;
    if ((int)blockIdx.x < ablocks) {
        const int idx = blockIdx.x * 256 + tid;
        const int r  = idx >> 7;
        const int k8 = (idx & 127) * 8;
        const float* ap; int astr, kl;
        if (k8 < 256)      { ap = x; astr = 256; kl = k8;       }
        else if (k8 < 768) { ap = h; astr = 512; kl = k8 - 256; }
        else if (k8 < 896) { ap = s; astr = 128; kl = k8 - 768; }
        else               { ap = t; astr = 128; kl = k8 - 896; }
        const float4* src = reinterpret_cast<const float4*>(
            ap + (size_t)r * astr + kl);
        const float4 f0 = src[0], f1 = src[1];
        __half2 h0 = __floats2half2_rn(f0.x, f0.y);
        __half2 h1 = __floats2half2_rn(f0.z, f0.w);
        __half2 h2 = __floats2half2_rn(f1.x, f1.y);
        __half2 h3 = __floats2half2_rn(f1.z, f1.w);
        uint4 v = make_uint4(*(uint32_t*)&h0, *(uint32_t*)&h1,
                             *(uint32_t*)&h2, *(uint32_t*)&h3);
        *reinterpret_cast<uint4*>(g_Af16 + (size_t)r * 1024 + k8) = v;
    } else {
        __shared__ float tile[32][33];
        const int wb = blockIdx.x - ablocks;      // 0..2047
        const int k0 = (wb & 31) * 32;
        const int r0 = (wb >> 5) * 32;
        const float* wp; int kl;
        if (k0 < 256)      { wp = Wx; kl = k0;       }
        else if (k0 < 768) { wp = Wh; kl = k0 - 256; }
        else if (k0 < 896) { wp = Ws; kl = k0 - 768; }
        else               { wp = Wt; kl = k0 - 896; }
        const int tx = tid & 31, ty = tid >> 5;
        const int r = r0 + tx;
        const int c = ((r >> 3) & 3) * 512 + (r >> 7) * 32 +
                      ((r >> 5) & 3) * 8 + (r & 7);
#pragma unroll
        for (int i = 0; i < 4; i++) {
            const int ky = ty + 8 * i;
            tile[tx][ky] = wp[(size_t)(kl + ky) * 2048 + c];
        }
        __syncthreads();
#pragma unroll
        for (int i = 0; i < 4; i++) {
            const int ky = ty + 8 * i;
            g_Wf16[(size_t)(r0 + ky) * 1024 + k0 + tx] =
                __half_as_ushort(__float2half_rn(tile[ky][tx]));
        }
    }
}

// ---- main GEMM + gates ------------------------------------------------------
__global__ __launch_bounds__(256, 2)
void lstm_gemm(const float* __restrict__ cin, const float* __restrict__ bh,
               float* __restrict__ out, int B)
{
    extern __shared__ __align__(1024) char smem[];
    const uint32_t sb = s2u(smem);
    const uint32_t mb_full  = sb + MBAR_OFF;        // 3 x 8B, count 256
    const uint32_t mb_empty = sb + MBAR_OFF + 24;   // 3 x 8B, count 8 (warps)
    const int tid  = threadIdx.x;
    const int wid  = tid >> 5;
    const int lane = tid & 31;
    const int gid  = lane >> 2;
    const int tig  = lane & 3;
    const int wm   = wid & 1;       // M half  (64 rows)
    const int wn   = wid >> 1;      // N quarter (32 preact cols)
    const int m0   = blockIdx.x * 128;
    const int by   = blockIdx.y;    // 32-hidden-col block

    float acc[4][4][4];
#pragma unroll
    for (int mt = 0; mt < 4; mt++)
#pragma unroll
        for (int nt = 0; nt < 4; nt++)
#pragma unroll
            for (int q = 0; q < 4; q++) acc[mt][nt][q] = 0.0f;

    const uint16_t* Abase = g_Af16 + (size_t)m0 * 1024;
    const uint16_t* Wbase = g_Wf16 + (size_t)by * 128 * 1024;

    // issue chunk q into stage stq; cp.async completion -> full[stq] arrival
    auto issue = [&](int q, int stq) {
        const uint32_t base = sb + stq * STAGE;
        const int kg = q * 64;
#pragma unroll
        for (int i = 0; i < 8; i++) {
            const int v   = tid + i * 256;
            const int mat = v >> 10;
            const int row = (v >> 3) & 127;
            const int seg = v & 7;
            const uint32_t dst = base + mat * 16384 + row * 128 +
                                 (seg ^ (row & 7)) * 16;
            const uint16_t* src = (mat ? Wbase : Abase) +
                                  (size_t)row * 1024 + kg + seg * 8;
            asm volatile("cp.async.cg.shared.global [%0], [%1], 16;"
                         :: "r"(dst), "l"(src));
        }
        cp_arrive_noinc(mb_full + 8 * stq);
    };

    // one k16 step of the chunk in stage st
    auto compute_ks = [&](int st, int ks) {
        const uint32_t ab = sb + st * STAGE;
        const uint32_t bb = ab + 16384;
        uint32_t a[4][4];
#pragma unroll
        for (int mt = 0; mt < 4; mt++) {
            const int row = wm * 64 + mt * 16 + (lane & 7) +
                            8 * ((lane >> 3) & 1);
            const int seg = 2 * ks + ((lane >> 4) & 1);
            const uint32_t addr = ab + row * 128 + (seg ^ (row & 7)) * 16;
            ldsm4(a[mt][0], a[mt][1], a[mt][2], a[mt][3], addr);
        }
        uint32_t b[4][2];
#pragma unroll
        for (int np = 0; np < 2; np++) {
            const int row = wn * 32 + np * 16 + (lane & 7) +
                            8 * ((lane >> 4) & 1);
            const int seg = 2 * ks + ((lane >> 3) & 1);
            const uint32_t addr = bb + row * 128 + (seg ^ (row & 7)) * 16;
            ldsm4(b[2 * np][0], b[2 * np][1],
                  b[2 * np + 1][0], b[2 * np + 1][1], addr);
        }
#pragma unroll
        for (int mt = 0; mt < 4; mt++)
#pragma unroll
            for (int nt = 0; nt < 4; nt++)
                mma_f16(acc[mt][nt], a[mt], b[nt][0], b[nt][1]);
    };

    // prologue: bias, mbarrier init, 2 stages in flight
    if (tid < 128) {
        const int g = tid >> 5, jl = tid & 31;
        ((float*)(smem + BIAS_OFF))[tid] = bh[g * 512 + by * 32 + jl];
    }
    if (tid == 0) {
#pragma unroll
        for (int i = 0; i < NST; i++) {
            mbar_init(mb_full + 8 * i, 256);
            mbar_init(mb_empty + 8 * i, 8);
        }
    }
    __syncthreads();
    issue(0, 0);
    issue(1, 1);

    // mainloop: wait full -> ks0 -> (wait empty + issue, overlapped) -> ks1-3
#pragma unroll 1
    for (int s = 0; s < 16; s++) {
        const int d  = (s * 11) >> 5;        // s / 3 for s < 18
        const int st = s - 3 * d;
        mbar_wait(mb_full + 8 * st, d & 1);
        compute_ks(st, 0);
        const int q = s + 2;
        if (q < 16) {
            const int dq  = (q * 11) >> 5;
            const int stq = q - 3 * dq;
            if (q >= NST)
                mbar_wait(mb_empty + 8 * stq, (dq - 1) & 1);
            issue(q, stq);
        }
        compute_ks(st, 1);
        compute_ks(st, 2);
        compute_ks(st, 3);
        if (lane == 0)
            mbar_arrive(mb_empty + 8 * st);
    }

    // epilogue: register-local gates, per-warp retirement (no final sync)
    const float* bhs = (const float*)(smem + BIAS_OFF);
    const int jl0 = wn * 8 + 2 * tig;         // hidden col within 32-block
    const int jg  = by * 32 + jl0;
#pragma unroll
    for (int mt = 0; mt < 4; mt++) {
#pragma unroll
        for (int rh = 0; rh < 2; rh++) {
            const int row = m0 + wm * 64 + mt * 16 + gid + 8 * rh;
            const float2 cv = *reinterpret_cast<const float2*>(
                cin + (size_t)row * 512 + jg);
            float hn[2], cn[2];
#pragma unroll
            for (int e = 0; e < 2; e++) {
                const int ci = rh * 2 + e;
                const float pi = acc[mt][0][ci] + bhs[0 * 32 + jl0 + e];
                const float pf = acc[mt][1][ci] + bhs[1 * 32 + jl0 + e];
                const float po = acc[mt][2][ci] + bhs[2 * 32 + jl0 + e];
                const float pc = acc[mt][3][ci] + bhs[3 * 32 + jl0 + e];
                const float ig = sigm_a(pi);
                const float fg = sigm_a(pf);
                const float og = sigm_a(po);
                const float cg = tanh_a(pc);
                const float c_ = (e ? cv.y : cv.x);
                cn[e] = fg * c_ + ig * cg;
                hn[e] = tanh_a(og * cn[e]);
            }
            *reinterpret_cast<float2*>(out + (size_t)row * 512 + jg) =
                make_float2(hn[0], hn[1]);
            *reinterpret_cast<float2*>(out + (size_t)B * 512 +
                                       (size_t)row * 512 + jg) =
                make_float2(cn[0], cn[1]);
        }
    }
}

extern "C" void kernel_launch(void* const* d_in, const int* in_sizes, int n_in,
                              void* d_out, int out_size) {
    const float* x  = (const float*)d_in[0];
    const float* h  = (const float*)d_in[1];
    const float* c  = (const float*)d_in[2];
    const float* sp = (const float*)d_in[3];
    const float* tp = (const float*)d_in[4];
    const float* Wx = (const float*)d_in[5];
    const float* Wh = (const float*)d_in[6];
    const float* bh = (const float*)d_in[7];
    const float* Ws = (const float*)d_in[8];
    const float* Wt = (const float*)d_in[9];
    float* out = (float*)d_out;

    const int B = in_sizes[0] / 256;   // x is [B, 256]
    const int ablocks = (B * 128) / 256;

    prep<<<ablocks + 2048, 256>>>(x, h, sp, tp, Wx, Wh, Ws, Wt, ablocks);

    static int smem_set = 0;
    if (!smem_set) {
        cudaFuncSetAttribute(lstm_gemm,
                             cudaFuncAttributeMaxDynamicSharedMemorySize, SMEM);
        smem_set = 1;
    }
    lstm_gemm<<<dim3(B / 128, 16), 256, SMEM>>>(c, bh, out, B);
}

// round 11
// speedup vs baseline: 3.9805x; 1.0080x over previous
#include <cuda_runtime.h>
#include <cuda_fp16.h>
#include <cstdint>

// ---------------------------------------------------------------------------
// Fused LSTM cell, 2-kernel plan (R11):
//   1) prep: activations -> g_Af16 [16384x1024] (16 elems/thread, MLP=2);
//      W -> g_Wf16 [2048x1024] transposed + gate-interleave permuted.
//   2) lstm_gemm: cp.async 3-stage K64 mbarrier pipeline, ldmatrix +
//      mma.m16n8k16.f16, CTA 128x128, 8 warps (2Mx4N), 2 CTAs/SM.
// R11 vs R10:
//   - ks-rotation: warp w computes k16 steps in order (kk+wid)&3 -> de-phases
//     the post-barrier LDSM convoy across warps
//   - epilogue: cin loads software-pipelined one mt ahead
//   - cvtA: 16 elems/thread
// ---------------------------------------------------------------------------

__device__ static __align__(16) uint16_t g_Af16[16384ull * 1024ull];
__device__ static __align__(16) uint16_t g_Wf16[2048ull * 1024ull];

static constexpr int NST      = 3;
static constexpr int STAGE    = 32768;              // A 16KB + B 16KB
static constexpr int BIAS_OFF = NST * STAGE;        // 98304
static constexpr int MBAR_OFF = BIAS_OFF + 512;     // 98816: full[3], empty[3]
static constexpr int SMEM     = MBAR_OFF + 64;      // 98880

__device__ __forceinline__ uint32_t s2u(const void* p) {
    uint32_t a;
    asm("{ .reg .u64 t; cvta.to.shared.u64 t, %1; cvt.u32.u64 %0, t; }"
        : "=r"(a) : "l"(p));
    return a;
}
__device__ __forceinline__ void mbar_init(uint32_t mb, uint32_t cnt) {
    asm volatile("mbarrier.init.shared.b64 [%0], %1;" :: "r"(mb), "r"(cnt)
                 : "memory");
}
__device__ __forceinline__ void mbar_arrive(uint32_t mb) {
    asm volatile("mbarrier.arrive.shared.b64 _, [%0];" :: "r"(mb) : "memory");
}
__device__ __forceinline__ void cp_arrive_noinc(uint32_t mb) {
    asm volatile("cp.async.mbarrier.arrive.noinc.shared.b64 [%0];" :: "r"(mb)
                 : "memory");
}
__device__ __forceinline__ void mbar_wait(uint32_t mb, uint32_t parity) {
    asm volatile(
        "{\n\t.reg .pred P;\n\t"
        "WL_%=:\n\t"
        "mbarrier.try_wait.parity.acquire.cta.shared::cta.b64 P, [%0], %1, 0x989680;\n\t"
        "@P bra WD_%=;\n\t"
        "bra WL_%=;\n\t"
        "WD_%=:\n\t}"
        :: "r"(mb), "r"(parity) : "memory");
}
__device__ __forceinline__ void ldsm4(uint32_t& r0, uint32_t& r1,
                                      uint32_t& r2, uint32_t& r3, uint32_t a) {
    asm volatile("ldmatrix.sync.aligned.m8n8.x4.shared.b16 {%0,%1,%2,%3}, [%4];"
                 : "=r"(r0), "=r"(r1), "=r"(r2), "=r"(r3) : "r"(a));
}
__device__ __forceinline__ void mma_f16(float* d, const uint32_t* a,
                                        uint32_t b0, uint32_t b1) {
    asm volatile(
        "mma.sync.aligned.m16n8k16.row.col.f32.f16.f16.f32 "
        "{%0,%1,%2,%3}, {%4,%5,%6,%7}, {%8,%9}, {%0,%1,%2,%3};\n"
        : "+f"(d[0]), "+f"(d[1]), "+f"(d[2]), "+f"(d[3])
        : "r"(a[0]), "r"(a[1]), "r"(a[2]), "r"(a[3]), "r"(b0), "r"(b1));
}
__device__ __forceinline__ float tanh_a(float x) {
    float y;
    asm("tanh.approx.f32 %0, %1;" : "=f"(y) : "f"(x));
    return y;
}
__device__ __forceinline__ float sigm_a(float x) {
    return fmaf(tanh_a(0.5f * x), 0.5f, 0.5f);
}

// ---- prepass: activations + weights -> f16 scratch -------------------------
__global__ __launch_bounds__(256)
void prep(const float* __restrict__ x, const float* __restrict__ h,
          const float* __restrict__ s, const float* __restrict__ t,
          const float* __restrict__ Wx, const float* __restrict__ Wh,
          const float* __restrict__ Ws, const float* __restrict__ Wt,
          int ablocks) {
    const int tid = threadIdx.x;
    if ((int)blockIdx.x < ablocks) {
        // 16 elems/thread: row = idx>>6, k16 = (idx&63)*16
        const int idx = blockIdx.x * 256 + tid;
        const int r   = idx >> 6;
        const int k16 = (idx & 63) * 16;
        const float* ap; int astr, kl;
        if (k16 < 256)      { ap = x; astr = 256; kl = k16;       }
        else if (k16 < 768) { ap = h; astr = 512; kl = k16 - 256; }
        else if (k16 < 896) { ap = s; astr = 128; kl = k16 - 768; }
        else                { ap = t; astr = 128; kl = k16 - 896; }
        const float4* src = reinterpret_cast<const float4*>(
            ap + (size_t)r * astr + kl);
        const float4 f0 = src[0], f1 = src[1], f2 = src[2], f3 = src[3];
        __half2 h0 = __floats2half2_rn(f0.x, f0.y);
        __half2 h1 = __floats2half2_rn(f0.z, f0.w);
        __half2 h2 = __floats2half2_rn(f1.x, f1.y);
        __half2 h3 = __floats2half2_rn(f1.z, f1.w);
        __half2 h4 = __floats2half2_rn(f2.x, f2.y);
        __half2 h5 = __floats2half2_rn(f2.z, f2.w);
        __half2 h6 = __floats2half2_rn(f3.x, f3.y);
        __half2 h7 = __floats2half2_rn(f3.z, f3.w);
        uint4* dst = reinterpret_cast<uint4*>(g_Af16 + (size_t)r * 1024 + k16);
        dst[0] = make_uint4(*(uint32_t*)&h0, *(uint32_t*)&h1,
                            *(uint32_t*)&h2, *(uint32_t*)&h3);
        dst[1] = make_uint4(*(uint32_t*)&h4, *(uint32_t*)&h5,
                            *(uint32_t*)&h6, *(uint32_t*)&h7);
    } else {
        __shared__ float tile[32][33];
        const int wb = blockIdx.x - ablocks;      // 0..2047
        const int k0 = (wb & 31) * 32;
        const int r0 = (wb >> 5) * 32;
        const float* wp; int kl;
        if (k0 < 256)      { wp = Wx; kl = k0;       }
        else if (k0 < 768) { wp = Wh; kl = k0 - 256; }
        else if (k0 < 896) { wp = Ws; kl = k0 - 768; }
        else               { wp = Wt; kl = k0 - 896; }
        const int tx = tid & 31, ty = tid >> 5;
        const int r = r0 + tx;
        const int c = ((r >> 3) & 3) * 512 + (r >> 7) * 32 +
                      ((r >> 5) & 3) * 8 + (r & 7);
#pragma unroll
        for (int i = 0; i < 4; i++) {
            const int ky = ty + 8 * i;
            tile[tx][ky] = wp[(size_t)(kl + ky) * 2048 + c];
        }
        __syncthreads();
#pragma unroll
        for (int i = 0; i < 4; i++) {
            const int ky = ty + 8 * i;
            g_Wf16[(size_t)(r0 + ky) * 1024 + k0 + tx] =
                __half_as_ushort(__float2half_rn(tile[ky][tx]));
        }
    }
}

// ---- main GEMM + gates ------------------------------------------------------
__global__ __launch_bounds__(256, 2)
void lstm_gemm(const float* __restrict__ cin, const float* __restrict__ bh,
               float* __restrict__ out, int B)
{
    extern __shared__ __align__(1024) char smem[];
    const uint32_t sb = s2u(smem);
    const uint32_t mb_full  = sb + MBAR_OFF;        // 3 x 8B, count 256
    const uint32_t mb_empty = sb + MBAR_OFF + 24;   // 3 x 8B, count 8 (warps)
    const int tid  = threadIdx.x;
    const int wid  = tid >> 5;
    const int lane = tid & 31;
    const int gid  = lane >> 2;
    const int tig  = lane & 3;
    const int wm   = wid & 1;       // M half  (64 rows)
    const int wn   = wid >> 1;      // N quarter (32 preact cols)
    const int m0   = blockIdx.x * 128;
    const int by   = blockIdx.y;    // 32-hidden-col block

    float acc[4][4][4];
#pragma unroll
    for (int mt = 0; mt < 4; mt++)
#pragma unroll
        for (int nt = 0; nt < 4; nt++)
#pragma unroll
            for (int q = 0; q < 4; q++) acc[mt][nt][q] = 0.0f;

    const uint16_t* Abase = g_Af16 + (size_t)m0 * 1024;
    const uint16_t* Wbase = g_Wf16 + (size_t)by * 128 * 1024;

    // issue chunk q into stage stq; cp.async completion -> full[stq] arrival
    auto issue = [&](int q, int stq) {
        const uint32_t base = sb + stq * STAGE;
        const int kg = q * 64;
#pragma unroll
        for (int i = 0; i < 8; i++) {
            const int v   = tid + i * 256;
            const int mat = v >> 10;
            const int row = (v >> 3) & 127;
            const int seg = v & 7;
            const uint32_t dst = base + mat * 16384 + row * 128 +
                                 (seg ^ (row & 7)) * 16;
            const uint16_t* src = (mat ? Wbase : Abase) +
                                  (size_t)row * 1024 + kg + seg * 8;
            asm volatile("cp.async.cg.shared.global [%0], [%1], 16;"
                         :: "r"(dst), "l"(src));
        }
        cp_arrive_noinc(mb_full + 8 * stq);
    };

    // one k16 step of the chunk in stage st
    auto compute_ks = [&](int st, int ks) {
        const uint32_t ab = sb + st * STAGE;
        const uint32_t bb = ab + 16384;
        uint32_t a[4][4];
#pragma unroll
        for (int mt = 0; mt < 4; mt++) {
            const int row = wm * 64 + mt * 16 + (lane & 7) +
                            8 * ((lane >> 3) & 1);
            const int seg = 2 * ks + ((lane >> 4) & 1);
            const uint32_t addr = ab + row * 128 + (seg ^ (row & 7)) * 16;
            ldsm4(a[mt][0], a[mt][1], a[mt][2], a[mt][3], addr);
        }
        uint32_t b[4][2];
#pragma unroll
        for (int np = 0; np < 2; np++) {
            const int row = wn * 32 + np * 16 + (lane & 7) +
                            8 * ((lane >> 4) & 1);
            const int seg = 2 * ks + ((lane >> 3) & 1);
            const uint32_t addr = bb + row * 128 + (seg ^ (row & 7)) * 16;
            ldsm4(b[2 * np][0], b[2 * np][1],
                  b[2 * np + 1][0], b[2 * np + 1][1], addr);
        }
#pragma unroll
        for (int mt = 0; mt < 4; mt++)
#pragma unroll
            for (int nt = 0; nt < 4; nt++)
                mma_f16(acc[mt][nt], a[mt], b[nt][0], b[nt][1]);
    };

    // prologue: bias, mbarrier init, 2 stages in flight
    if (tid < 128) {
        const int g = tid >> 5, jl = tid & 31;
        ((float*)(smem + BIAS_OFF))[tid] = bh[g * 512 + by * 32 + jl];
    }
    if (tid == 0) {
#pragma unroll
        for (int i = 0; i < NST; i++) {
            mbar_init(mb_full + 8 * i, 256);
            mbar_init(mb_empty + 8 * i, 8);
        }
    }
    __syncthreads();
    issue(0, 0);
    issue(1, 1);

    // mainloop; warp w runs k16 steps in rotated order (kk+wid)&3
#pragma unroll 1
    for (int s = 0; s < 16; s++) {
        const int d  = (s * 11) >> 5;        // s / 3 for s < 18
        const int st = s - 3 * d;
        mbar_wait(mb_full + 8 * st, d & 1);
        compute_ks(st, wid & 3);
        const int q = s + 2;
        if (q < 16) {
            const int dq  = (q * 11) >> 5;
            const int stq = q - 3 * dq;
            if (q >= NST)
                mbar_wait(mb_empty + 8 * stq, (dq - 1) & 1);
            issue(q, stq);
        }
        compute_ks(st, (wid + 1) & 3);
        compute_ks(st, (wid + 2) & 3);
        compute_ks(st, (wid + 3) & 3);
        if (lane == 0)
            mbar_arrive(mb_empty + 8 * st);
    }

    // epilogue: register-local gates; cin loads pipelined one mt ahead
    const float* bhs = (const float*)(smem + BIAS_OFF);
    const int jl0 = wn * 8 + 2 * tig;         // hidden col within 32-block
    const int jg  = by * 32 + jl0;
    const int rowbase = m0 + wm * 64 + gid;

    float2 cv[2];
    cv[0] = *reinterpret_cast<const float2*>(cin + (size_t)rowbase * 512 + jg);
    cv[1] = *reinterpret_cast<const float2*>(cin + (size_t)(rowbase + 8) * 512 + jg);
#pragma unroll
    for (int mt = 0; mt < 4; mt++) {
        float2 cvn[2];
        if (mt < 3) {
            const int rn = rowbase + (mt + 1) * 16;
            cvn[0] = *reinterpret_cast<const float2*>(
                cin + (size_t)rn * 512 + jg);
            cvn[1] = *reinterpret_cast<const float2*>(
                cin + (size_t)(rn + 8) * 512 + jg);
        }
#pragma unroll
        for (int rh = 0; rh < 2; rh++) {
            const int row = rowbase + mt * 16 + 8 * rh;
            float hn[2], cn[2];
#pragma unroll
            for (int e = 0; e < 2; e++) {
                const int ci = rh * 2 + e;
                const float pi = acc[mt][0][ci] + bhs[0 * 32 + jl0 + e];
                const float pf = acc[mt][1][ci] + bhs[1 * 32 + jl0 + e];
                const float po = acc[mt][2][ci] + bhs[2 * 32 + jl0 + e];
                const float pc = acc[mt][3][ci] + bhs[3 * 32 + jl0 + e];
                const float ig = sigm_a(pi);
                const float fg = sigm_a(pf);
                const float og = sigm_a(po);
                const float cg = tanh_a(pc);
                const float c_ = (e ? cv[rh].y : cv[rh].x);
                cn[e] = fg * c_ + ig * cg;
                hn[e] = tanh_a(og * cn[e]);
            }
            *reinterpret_cast<float2*>(out + (size_t)row * 512 + jg) =
                make_float2(hn[0], hn[1]);
            *reinterpret_cast<float2*>(out + (size_t)B * 512 +
                                       (size_t)row * 512 + jg) =
                make_float2(cn[0], cn[1]);
        }
        cv[0] = cvn[0];
        cv[1] = cvn[1];
    }
}

extern "C" void kernel_launch(void* const* d_in, const int* in_sizes, int n_in,
                              void* d_out, int out_size) {
    const float* x  = (const float*)d_in[0];
    const float* h  = (const float*)d_in[1];
    const float* c  = (const float*)d_in[2];
    const float* sp = (const float*)d_in[3];
    const float* tp = (const float*)d_in[4];
    const float* Wx = (const float*)d_in[5];
    const float* Wh = (const float*)d_in[6];
    const float* bh = (const float*)d_in[7];
    const float* Ws = (const float*)d_in[8];
    const float* Wt = (const float*)d_in[9];
    float* out = (float*)d_out;

    const int B = in_sizes[0] / 256;   // x is [B, 256]
    const int ablocks = (B * 1024) / (256 * 16);

    prep<<<ablocks + 2048, 256>>>(x, h, sp, tp, Wx, Wh, Ws, Wt, ablocks);

    static int smem_set = 0;
    if (!smem_set) {
        cudaFuncSetAttribute(lstm_gemm,
                             cudaFuncAttributeMaxDynamicSharedMemorySize, SMEM);
        smem_set = 1;
    }
    lstm_gemm<<<dim3(B / 128, 16), 256, SMEM>>>(c, bh, out, B);
}